// round 9
// baseline (speedup 1.0000x reference)
#include <cuda_runtime.h>
#include <cuda_fp16.h>
#include <math.h>
#include <cstdint>

#define HD 2048
#define ID 1408
#define NE 16
#define TK 4
#define NT 1024
#define SID 2816
#define RSCALE 2.5f

// ---------------- scratch ----------------
__device__ int    d_cnt[NE];
__device__ int    d_tok[NE * NT];
__device__ float  d_wt [NE * NT];
// fp16 pair-permuted copies (K-groups of 16 stored as [p0,p4,p1,p5,p2,p6,p3,p7])
__device__ __half w_g16[NE * ID * HD];
__device__ __half w_u16[NE * ID * HD];
__device__ __half w_d16[NE * HD * ID];
__device__ __half sw_g16[SID * HD];
__device__ __half sw_u16[SID * HD];
__device__ __half sw_d16[HD * SID];
__device__ __half x16  [NT * HD];
__device__ __half h_r16[NE * NT * ID];
__device__ __half h_s16[NT * SID];

// ---------------- PTX helpers ----------------
__device__ __forceinline__ uint32_t smem_u32(const void* p) {
    uint32_t a;
    asm("{ .reg .u64 t; cvta.to.shared.u64 t, %1; cvt.u32.u64 %0, t; }"
        : "=r"(a) : "l"(p));
    return a;
}
#define CP_ASYNC(dst, src, sz) \
    asm volatile("cp.async.cg.shared.global [%0], [%1], 16, %2;" \
                 :: "r"(dst), "l"(src), "r"(sz) : "memory")
#define CP_COMMIT() asm volatile("cp.async.commit_group;" ::: "memory")
#define CP_WAIT(n)  asm volatile("cp.async.wait_group %0;" :: "n"(n) : "memory")

__device__ __forceinline__ void mma16(float* c, const uint32_t* a, const uint32_t* b) {
    asm volatile(
        "mma.sync.aligned.m16n8k16.row.col.f32.f16.f16.f32 "
        "{%0,%1,%2,%3}, {%4,%5,%6,%7}, {%8,%9}, {%0,%1,%2,%3};"
        : "+f"(c[0]), "+f"(c[1]), "+f"(c[2]), "+f"(c[3])
        : "r"(a[0]), "r"(a[1]), "r"(a[2]), "r"(a[3]), "r"(b[0]), "r"(b[1]));
}
__device__ __forceinline__ float silu(float g) { return g / (1.f + __expf(-g)); }
__device__ __forceinline__ uint32_t h2u(__half2 h) {
    uint32_t u; *(__half2*)&u = h; return u;
}

// smem rows: 64B data (32 fp16, permuted) + 32B pad = 96B (12 uint2)
#define ROWB 96
#define ROWU2 12

// ---------------- init / converts ----------------
__global__ void init_kernel() {
    if (threadIdx.x < NE) d_cnt[threadIdx.x] = 0;
}
// fp32 -> fp16, permuting each flat 16-element group to pair order
__global__ void conv_perm(const float4* __restrict__ src, uint4* __restrict__ dst) {
    const size_t t = (size_t)blockIdx.x * 256 + threadIdx.x;
    float4 f0 = src[4 * t], f1 = src[4 * t + 1], f2 = src[4 * t + 2], f3 = src[4 * t + 3];
    const float f[16] = { f0.x, f0.y, f0.z, f0.w, f1.x, f1.y, f1.z, f1.w,
                          f2.x, f2.y, f2.z, f2.w, f3.x, f3.y, f3.z, f3.w };
    uint32_t h[8];
    #pragma unroll
    for (int s = 0; s < 8; s++) {
        const int j = (s & 1) ? ((s >> 1) + 4) : (s >> 1);
        h[s] = h2u(__floats2half2_rn(f[2 * j], f[2 * j + 1]));
    }
    dst[2 * t]     = make_uint4(h[0], h[1], h[2], h[3]);
    dst[2 * t + 1] = make_uint4(h[4], h[5], h[6], h[7]);
}

// ---------------- gate (raw fp32 x) ----------------
__global__ void gate_kernel(const float* __restrict__ x,
                            const float* __restrict__ gw,
                            const float* __restrict__ gb) {
    const int t = blockIdx.x;
    __shared__ float s_sc[NE];
    const int wid = threadIdx.x >> 5;
    const int lane = threadIdx.x & 31;
    const float* xr = x + (size_t)t * HD;
    const float* wr = gw + (size_t)wid * HD;
    float acc = 0.f;
    for (int k = lane; k < HD; k += 32) acc += xr[k] * wr[k];
    #pragma unroll
    for (int o = 16; o; o >>= 1) acc += __shfl_xor_sync(0xffffffffu, acc, o);
    if (lane == 0) s_sc[wid] = 1.f / (1.f + expf(-acc)) + gb[wid];
    __syncthreads();
    if (threadIdx.x != 0) return;

    float sc[NE];
    #pragma unroll
    for (int e = 0; e < NE; e++) sc[e] = s_sc[e];
    float gs[4];
    #pragma unroll
    for (int g = 0; g < 4; g++) {
        float m = sc[g * 4];
        #pragma unroll
        for (int j = 1; j < 4; j++) m = fmaxf(m, sc[g * 4 + j]);
        gs[g] = m;
    }
    int g0 = 0;
    for (int g = 1; g < 4; g++) if (gs[g] > gs[g0]) g0 = g;
    int g1 = -1;
    for (int g = 0; g < 4; g++) {
        if (g == g0) continue;
        if (g1 < 0 || gs[g] > gs[g1]) g1 = g;
    }
    float masked[NE];
    #pragma unroll
    for (int e = 0; e < NE; e++) {
        int g = e >> 2;
        masked[e] = (g == g0 || g == g1) ? sc[e] : 0.f;
    }
    int idx[TK]; float w[TK]; bool used[NE];
    #pragma unroll
    for (int e = 0; e < NE; e++) used[e] = false;
    float wsum = 0.f;
    for (int k = 0; k < TK; k++) {
        int best = -1;
        for (int e = 0; e < NE; e++) {
            if (used[e]) continue;
            if (best < 0 || masked[e] > masked[best]) best = e;
        }
        used[best] = true;
        idx[k] = best; w[k] = masked[best]; wsum += masked[best];
    }
    const float inv = 1.f / (wsum + 1e-6f);
    for (int k = 0; k < TK; k++) {
        int e = idx[k];
        int pos = atomicAdd(&d_cnt[e], 1);
        d_tok[e * NT + pos] = t;
        d_wt [e * NT + pos] = w[k] * inv * RSCALE;
    }
}

// ---------------- GEMM1 fp16: dual (gate,up) + SiLU ------------------------
// Tile 128M x 128N dual, warp 64x32 dual, Kc=32, 3-stage.
// Stage: A 128x96B @0 | G 128x96B @12288 | U @24576 ; stride 36864
#define G1_STAGE 36864
#define G1_SMEM  (512 + 3 * G1_STAGE)
template <bool GATHER>
__global__ void __launch_bounds__(256, 1)
gemm1_h(const __half* __restrict__ X,
        const __half* __restrict__ Wg_, const __half* __restrict__ Wu_,
        __half* __restrict__ H_, int ldH, int K) {
    const int e = blockIdx.z;
    int M; const int* toks = nullptr; const __half *Wg, *Wu; __half* Ho;
    if (GATHER) {
        M = d_cnt[e]; toks = d_tok + e * NT;
        Wg = Wg_ + (size_t)e * ID * HD;
        Wu = Wu_ + (size_t)e * ID * HD;
        Ho = H_ + (size_t)e * NT * ID;
    } else {
        M = NT; Wg = Wg_; Wu = Wu_; Ho = H_;
    }
    const int m0 = blockIdx.y * 128;
    if (m0 >= M) return;
    const int n0 = blockIdx.x * 128;

    extern __shared__ char smem[];
    int* s_tok = (int*)smem;
    const int tid = threadIdx.x, lane = tid & 31, wid = tid >> 5;
    const int wr = wid >> 2, wc = wid & 3;
    if (GATHER && tid < 128) s_tok[tid] = (m0 + tid < M) ? toks[m0 + tid] : 0;
    __syncthreads();

    // loader: thread pair covers one row each of A, G, U (32B halves)
    const int rL = tid >> 1, hL = (tid & 1) * 32;
    const bool aok = (m0 + rL) < M;
    const int ar = GATHER ? (aok ? s_tok[rL] : 0) : (aok ? m0 + rL : 0);
    const char* Ap = (const char*)(X + (size_t)ar * K) + hL;
    const char* Gp = (const char*)(Wg + (size_t)(n0 + rL) * K) + hL;
    const char* Up = (const char*)(Wu + (size_t)(n0 + rL) * K) + hL;
    const uint32_t sb = smem_u32(smem) + 512;
    const uint32_t dA = sb + rL * ROWB + hL;
    const uint32_t dG = dA + 12288;
    const uint32_t dU = dA + 24576;
    const uint32_t szA = aok ? 16u : 0u;

    const int C = K >> 5;   // 32 cols per chunk
    auto load = [&](int c, int buf) {
        const int off = c * 64;
        const uint32_t b = buf * G1_STAGE;
        CP_ASYNC(dA + b,      Ap + off,      szA);
        CP_ASYNC(dA + b + 16, Ap + off + 16, szA);
        CP_ASYNC(dG + b,      Gp + off,      16);
        CP_ASYNC(dG + b + 16, Gp + off + 16, 16);
        CP_ASYNC(dU + b,      Up + off,      16);
        CP_ASYNC(dU + b + 16, Up + off + 16, 16);
    };

    float cg[4][4][4] = {}, cu[4][4][4] = {};
    #pragma unroll
    for (int s = 0; s < 2; s++) { if (s < C) load(s, s); CP_COMMIT(); }

    const int l4 = lane >> 2, lm = lane & 3;
    const int a_off = (wr * 64 + l4) * ROWU2 + lm;
    const int g_off = 1536 + (wc * 32 + l4) * ROWU2 + lm;   // 12288B/8
    #pragma unroll 1
    for (int c = 0; c < C; c++) {
        CP_WAIT(1);
        __syncthreads();
        const int nc = c + 2;
        if (nc < C) load(nc, nc % 3);
        CP_COMMIT();
        const uint2* S = (const uint2*)(smem + 512 + (c % 3) * G1_STAGE);
        #pragma unroll
        for (int ks = 0; ks < 2; ks++) {
            uint32_t a[4][4];
            #pragma unroll
            for (int mi = 0; mi < 4; mi++) {
                const uint2 p = S[a_off + mi * (16 * ROWU2) + ks * 4];
                const uint2 q = S[a_off + mi * (16 * ROWU2) + 8 * ROWU2 + ks * 4];
                a[mi][0] = p.x; a[mi][1] = q.x; a[mi][2] = p.y; a[mi][3] = q.y;
            }
            #pragma unroll
            for (int ni = 0; ni < 4; ni++) {
                const uint2 vg = S[g_off + ni * (8 * ROWU2) + ks * 4];
                const uint2 vu = S[g_off + 1536 + ni * (8 * ROWU2) + ks * 4];
                uint32_t bg[2] = { vg.x, vg.y };
                uint32_t bu[2] = { vu.x, vu.y };
                #pragma unroll
                for (int mi = 0; mi < 4; mi++) {
                    mma16(cg[mi][ni], a[mi], bg);
                    mma16(cu[mi][ni], a[mi], bu);
                }
            }
        }
    }
    // epilogue: silu(g)*u -> fp16 pair-permuted; two 16-col groups per warp
    #pragma unroll
    for (int mi = 0; mi < 4; mi++)
        #pragma unroll
        for (int h = 0; h < 2; h++) {
            const int r = m0 + wr * 64 + mi * 16 + l4 + h * 8;
            if (r >= M) continue;
            __half* hrow = Ho + (size_t)r * ldH + n0 + wc * 32;
            #pragma unroll
            for (int grp = 0; grp < 2; grp++) {
                const int n0i = grp * 2, n1i = grp * 2 + 1;
                const float v0 = silu(cg[mi][n0i][2 * h + 0]) * cu[mi][n0i][2 * h + 0];
                const float v1 = silu(cg[mi][n0i][2 * h + 1]) * cu[mi][n0i][2 * h + 1];
                const float v2 = silu(cg[mi][n1i][2 * h + 0]) * cu[mi][n1i][2 * h + 0];
                const float v3 = silu(cg[mi][n1i][2 * h + 1]) * cu[mi][n1i][2 * h + 1];
                uint2 val = { h2u(__floats2half2_rn(v0, v1)),
                              h2u(__floats2half2_rn(v2, v3)) };
                ((uint2*)(hrow + grp * 16))[lm] = val;
            }
        }
}

// ---------------- GEMM2 fp16: down --------------------------------------
// Tile 128M x 256N, warp 64x64, Kc=32, 3-stage. Stage: A 128 @0 | B 256 @12288
#define G2_STAGE 36864
#define G2_SMEM  (1024 + 3 * G2_STAGE)
template <bool ROUTED>
__global__ void __launch_bounds__(256, 1)
gemm2_h(const __half* __restrict__ Hin_, const __half* __restrict__ Wd_,
        float* __restrict__ Out, int K) {
    const int e = blockIdx.z;
    int M; const __half *Hin, *Wd; const int* toks = nullptr; const float* wts = nullptr;
    if (ROUTED) {
        M = d_cnt[e];
        Hin = Hin_ + (size_t)e * NT * ID;
        Wd  = Wd_  + (size_t)e * HD * ID;
        toks = d_tok + e * NT; wts = d_wt + e * NT;
    } else {
        M = NT; Hin = Hin_; Wd = Wd_;
    }
    const int m0 = blockIdx.y * 128;
    if (m0 >= M) return;
    const int n0 = blockIdx.x * 256;

    extern __shared__ char smem[];
    int*   s_tok = (int*)smem;
    float* s_wt  = (float*)(smem + 512);
    const int tid = threadIdx.x, lane = tid & 31, wid = tid >> 5;
    const int wr = wid >> 2, wc = wid & 3;
    if (ROUTED && tid < 128) {
        const bool ok = m0 + tid < M;
        s_tok[tid] = ok ? toks[m0 + tid] : 0;
        s_wt [tid] = ok ? wts [m0 + tid] : 0.f;
    }
    __syncthreads();

    // loader: A row tid>>1 (32B half), B row tid (full 64B)
    const int rA = tid >> 1, hA = (tid & 1) * 32;
    const bool aok = (m0 + rA) < M;
    const char* Ap = (const char*)(Hin + (size_t)(aok ? m0 + rA : 0) * K) + hA;
    const char* Bp = (const char*)(Wd + (size_t)(n0 + tid) * K);
    const uint32_t sb = smem_u32(smem) + 1024;
    const uint32_t dA = sb + rA * ROWB + hA;
    const uint32_t dB = sb + 12288 + tid * ROWB;
    const uint32_t szA = aok ? 16u : 0u;

    const int C = K >> 5;
    auto load = [&](int c, int buf) {
        const int off = c * 64;
        const uint32_t b = buf * G2_STAGE;
        CP_ASYNC(dA + b,      Ap + off,      szA);
        CP_ASYNC(dA + b + 16, Ap + off + 16, szA);
        CP_ASYNC(dB + b,      Bp + off,      16);
        CP_ASYNC(dB + b + 16, Bp + off + 16, 16);
        CP_ASYNC(dB + b + 32, Bp + off + 32, 16);
        CP_ASYNC(dB + b + 48, Bp + off + 48, 16);
    };

    float acc[4][8][4] = {};
    #pragma unroll
    for (int s = 0; s < 2; s++) { if (s < C) load(s, s); CP_COMMIT(); }

    const int l4 = lane >> 2, lm = lane & 3;
    const int a_off = (wr * 64 + l4) * ROWU2 + lm;
    const int b_off = 1536 + (wc * 64 + l4) * ROWU2 + lm;
    #pragma unroll 1
    for (int c = 0; c < C; c++) {
        CP_WAIT(1);
        __syncthreads();
        const int nc = c + 2;
        if (nc < C) load(nc, nc % 3);
        CP_COMMIT();
        const uint2* S = (const uint2*)(smem + 1024 + (c % 3) * G2_STAGE);
        #pragma unroll
        for (int ks = 0; ks < 2; ks++) {
            uint32_t a[4][4];
            #pragma unroll
            for (int mi = 0; mi < 4; mi++) {
                const uint2 p = S[a_off + mi * (16 * ROWU2) + ks * 4];
                const uint2 q = S[a_off + mi * (16 * ROWU2) + 8 * ROWU2 + ks * 4];
                a[mi][0] = p.x; a[mi][1] = q.x; a[mi][2] = p.y; a[mi][3] = q.y;
            }
            #pragma unroll
            for (int ni = 0; ni < 8; ni++) {
                const uint2 vb = S[b_off + ni * (8 * ROWU2) + ks * 4];
                uint32_t b[2] = { vb.x, vb.y };
                #pragma unroll
                for (int mi = 0; mi < 4; mi++)
                    mma16(acc[mi][ni], a[mi], b);
            }
        }
    }
    #pragma unroll
    for (int mi = 0; mi < 4; mi++) {
        const int rl0 = wr * 64 + mi * 16 + l4;
        #pragma unroll
        for (int ni = 0; ni < 8; ni++) {
            const int cc = n0 + wc * 64 + ni * 8 + 2 * lm;
            #pragma unroll
            for (int h = 0; h < 2; h++) {
                const int rl = rl0 + h * 8;
                if (m0 + rl >= M) continue;
                const float v0 = acc[mi][ni][2 * h + 0];
                const float v1 = acc[mi][ni][2 * h + 1];
                if (ROUTED) {
                    const float w = s_wt[rl];
                    float* o = Out + (size_t)s_tok[rl] * HD + cc;
                    atomicAdd(o + 0, w * v0);
                    atomicAdd(o + 1, w * v1);
                } else {
                    float2 v = { v0, v1 };
                    *(float2*)(Out + (size_t)(m0 + rl) * HD + cc) = v;
                }
            }
        }
    }
}

// ---------------- launch ----------------
extern "C" void kernel_launch(void* const* d_in, const int* in_sizes, int n_in,
                              void* d_out, int out_size) {
    const float* x       = (const float*)d_in[0];
    const float* gate_w  = (const float*)d_in[1];
    const float* gate_b  = (const float*)d_in[2];
    const float* w_gate  = (const float*)d_in[3];
    const float* w_up    = (const float*)d_in[4];
    const float* w_down  = (const float*)d_in[5];
    const float* sw_gate = (const float*)d_in[6];
    const float* sw_up   = (const float*)d_in[7];
    const float* sw_down = (const float*)d_in[8];
    float* out = (float*)d_out;

    __half *wg16, *wu16, *wd16, *sg16, *su16, *sd16, *xh, *hr, *hs;
    cudaGetSymbolAddress((void**)&wg16, w_g16);
    cudaGetSymbolAddress((void**)&wu16, w_u16);
    cudaGetSymbolAddress((void**)&wd16, w_d16);
    cudaGetSymbolAddress((void**)&sg16, sw_g16);
    cudaGetSymbolAddress((void**)&su16, sw_u16);
    cudaGetSymbolAddress((void**)&sd16, sw_d16);
    cudaGetSymbolAddress((void**)&xh,   x16);
    cudaGetSymbolAddress((void**)&hr,   h_r16);
    cudaGetSymbolAddress((void**)&hs,   h_s16);

    cudaFuncSetAttribute(gemm1_h<true>,  cudaFuncAttributeMaxDynamicSharedMemorySize, G1_SMEM);
    cudaFuncSetAttribute(gemm1_h<false>, cudaFuncAttributeMaxDynamicSharedMemorySize, G1_SMEM);
    cudaFuncSetAttribute(gemm2_h<true>,  cudaFuncAttributeMaxDynamicSharedMemorySize, G2_SMEM);
    cudaFuncSetAttribute(gemm2_h<false>, cudaFuncAttributeMaxDynamicSharedMemorySize, G2_SMEM);

    init_kernel<<<1, 32>>>();
    conv_perm<<<11264, 256>>>((const float4*)w_gate,  (uint4*)wg16);
    conv_perm<<<11264, 256>>>((const float4*)w_up,    (uint4*)wu16);
    conv_perm<<<11264, 256>>>((const float4*)w_down,  (uint4*)wd16);
    conv_perm<<<1408,  256>>>((const float4*)sw_gate, (uint4*)sg16);
    conv_perm<<<1408,  256>>>((const float4*)sw_up,   (uint4*)su16);
    conv_perm<<<1408,  256>>>((const float4*)sw_down, (uint4*)sd16);
    conv_perm<<<512,   256>>>((const float4*)x,       (uint4*)xh);
    gate_kernel<<<NT, 512>>>(x, gate_w, gate_b);

    // routed gate/up + silu
    gemm1_h<true><<<dim3(ID / 128, NT / 128, NE), 256, G1_SMEM>>>(
        xh, wg16, wu16, hr, ID, HD);
    // shared gate/up + silu
    gemm1_h<false><<<dim3(SID / 128, NT / 128, 1), 256, G1_SMEM>>>(
        xh, sg16, su16, hs, SID, HD);
    // shared down: plain stores initialize d_out fully
    gemm2_h<false><<<dim3(HD / 256, NT / 128, 1), 256, G2_SMEM>>>(
        hs, sd16, out, SID);
    // routed down: atomic scatter-add
    gemm2_h<true><<<dim3(HD / 256, NT / 128, NE), 256, G2_SMEM>>>(
        hr, wd16, out, ID);
}

// round 10
// speedup vs baseline: 1.0626x; 1.0626x over previous
#include <cuda_runtime.h>
#include <cuda_fp16.h>
#include <math.h>
#include <cstdint>

#define HD 2048
#define ID 1408
#define NE 16
#define TK 4
#define NT 1024
#define SID 2816
#define RSCALE 2.5f

// ---------------- scratch ----------------
__device__ int    d_cnt[NE];
__device__ int    d_tok[NE * NT];
__device__ float  d_wt [NE * NT];
// natural K-major fp16 copies
__device__ __half w_g16[NE * ID * HD];
__device__ __half w_u16[NE * ID * HD];
__device__ __half w_d16[NE * HD * ID];
__device__ __half sw_g16[SID * HD];
__device__ __half sw_u16[SID * HD];
__device__ __half sw_d16[HD * SID];
__device__ __half x16  [NT * HD];
__device__ __half h_r16[NE * NT * ID];
__device__ __half h_s16[NT * SID];

// ---------------- PTX helpers ----------------
__device__ __forceinline__ uint32_t smem_u32(const void* p) {
    uint32_t a;
    asm("{ .reg .u64 t; cvta.to.shared.u64 t, %1; cvt.u32.u64 %0, t; }"
        : "=r"(a) : "l"(p));
    return a;
}
#define CP_ASYNC(dst, src, sz) \
    asm volatile("cp.async.cg.shared.global [%0], [%1], 16, %2;" \
                 :: "r"(dst), "l"(src), "r"(sz) : "memory")
#define CP_COMMIT() asm volatile("cp.async.commit_group;" ::: "memory")
#define CP_WAIT(n)  asm volatile("cp.async.wait_group %0;" :: "n"(n) : "memory")

__device__ __forceinline__ void mma16(float* c, const uint32_t* a, const uint32_t* b) {
    asm volatile(
        "mma.sync.aligned.m16n8k16.row.col.f32.f16.f16.f32 "
        "{%0,%1,%2,%3}, {%4,%5,%6,%7}, {%8,%9}, {%0,%1,%2,%3};"
        : "+f"(c[0]), "+f"(c[1]), "+f"(c[2]), "+f"(c[3])
        : "r"(a[0]), "r"(a[1]), "r"(a[2]), "r"(a[3]), "r"(b[0]), "r"(b[1]));
}
__device__ __forceinline__ void ldsm4(uint32_t* r, uint32_t addr) {
    asm volatile("ldmatrix.sync.aligned.m8n8.x4.shared.b16 {%0,%1,%2,%3}, [%4];"
        : "=r"(r[0]), "=r"(r[1]), "=r"(r[2]), "=r"(r[3]) : "r"(addr));
}
__device__ __forceinline__ float silu(float g) { return g / (1.f + __expf(-g)); }
__device__ __forceinline__ uint32_t h2u(__half2 h) {
    uint32_t u; *(__half2*)&u = h; return u;
}

// Dense rows: 64B = 32 fp16 (one k32 chunk). 16B-chunk swizzle:
// phys_chunk = chunk ^ ((row>>1)&3). Conflict-free for ldmatrix 8-row phases.

// ---------------- init / converts ----------------
__global__ void init_kernel() {
    if (threadIdx.x < NE) d_cnt[threadIdx.x] = 0;
}
// plain fp32 -> fp16, 16 elements per thread
__global__ void conv16(const float4* __restrict__ src, uint4* __restrict__ dst) {
    const size_t t = (size_t)blockIdx.x * 256 + threadIdx.x;
    float4 f0 = src[4 * t], f1 = src[4 * t + 1], f2 = src[4 * t + 2], f3 = src[4 * t + 3];
    dst[2 * t] = make_uint4(
        h2u(__floats2half2_rn(f0.x, f0.y)), h2u(__floats2half2_rn(f0.z, f0.w)),
        h2u(__floats2half2_rn(f1.x, f1.y)), h2u(__floats2half2_rn(f1.z, f1.w)));
    dst[2 * t + 1] = make_uint4(
        h2u(__floats2half2_rn(f2.x, f2.y)), h2u(__floats2half2_rn(f2.z, f2.w)),
        h2u(__floats2half2_rn(f3.x, f3.y)), h2u(__floats2half2_rn(f3.z, f3.w)));
}

// ---------------- gate (raw fp32 x) ----------------
__global__ void gate_kernel(const float* __restrict__ x,
                            const float* __restrict__ gw,
                            const float* __restrict__ gb) {
    const int t = blockIdx.x;
    __shared__ float s_sc[NE];
    const int wid = threadIdx.x >> 5;
    const int lane = threadIdx.x & 31;
    const float* xr = x + (size_t)t * HD;
    const float* wr = gw + (size_t)wid * HD;
    float acc = 0.f;
    for (int k = lane; k < HD; k += 32) acc += xr[k] * wr[k];
    #pragma unroll
    for (int o = 16; o; o >>= 1) acc += __shfl_xor_sync(0xffffffffu, acc, o);
    if (lane == 0) s_sc[wid] = 1.f / (1.f + expf(-acc)) + gb[wid];
    __syncthreads();
    if (threadIdx.x != 0) return;

    float sc[NE];
    #pragma unroll
    for (int e = 0; e < NE; e++) sc[e] = s_sc[e];
    float gs[4];
    #pragma unroll
    for (int g = 0; g < 4; g++) {
        float m = sc[g * 4];
        #pragma unroll
        for (int j = 1; j < 4; j++) m = fmaxf(m, sc[g * 4 + j]);
        gs[g] = m;
    }
    int g0 = 0;
    for (int g = 1; g < 4; g++) if (gs[g] > gs[g0]) g0 = g;
    int g1 = -1;
    for (int g = 0; g < 4; g++) {
        if (g == g0) continue;
        if (g1 < 0 || gs[g] > gs[g1]) g1 = g;
    }
    float masked[NE];
    #pragma unroll
    for (int e = 0; e < NE; e++) {
        int g = e >> 2;
        masked[e] = (g == g0 || g == g1) ? sc[e] : 0.f;
    }
    int idx[TK]; float w[TK]; bool used[NE];
    #pragma unroll
    for (int e = 0; e < NE; e++) used[e] = false;
    float wsum = 0.f;
    for (int k = 0; k < TK; k++) {
        int best = -1;
        for (int e = 0; e < NE; e++) {
            if (used[e]) continue;
            if (best < 0 || masked[e] > masked[best]) best = e;
        }
        used[best] = true;
        idx[k] = best; w[k] = masked[best]; wsum += masked[best];
    }
    const float inv = 1.f / (wsum + 1e-6f);
    for (int k = 0; k < TK; k++) {
        int e = idx[k];
        int pos = atomicAdd(&d_cnt[e], 1);
        d_tok[e * NT + pos] = t;
        d_wt [e * NT + pos] = w[k] * inv * RSCALE;
    }
}

// ---------------- GEMM1 fp16 ldmatrix: dual (gate,up) + SiLU ---------------
// Tile 128M x 64N dual, warp 64x16 dual, Kc=32, 4-stage.
// Stage 16384B: A 128x64B @0 | G 64x64B @8192 | U 64x64B @12288
#define G1_STAGE 16384
#define G1_SMEM  (512 + 4 * G1_STAGE)
template <bool GATHER>
__global__ void __launch_bounds__(256, 2)
gemm1_h(const __half* __restrict__ X,
        const __half* __restrict__ Wg_, const __half* __restrict__ Wu_,
        __half* __restrict__ H_, int ldH, int K) {
    const int e = blockIdx.z;
    int M; const int* toks = nullptr; const __half *Wg, *Wu; __half* Ho;
    if (GATHER) {
        M = d_cnt[e]; toks = d_tok + e * NT;
        Wg = Wg_ + (size_t)e * ID * HD;
        Wu = Wu_ + (size_t)e * ID * HD;
        Ho = H_ + (size_t)e * NT * ID;
    } else {
        M = NT; Wg = Wg_; Wu = Wu_; Ho = H_;
    }
    const int m0 = blockIdx.y * 128;
    if (m0 >= M) return;
    const int n0 = blockIdx.x * 64;

    extern __shared__ char smem[];
    int* s_tok = (int*)smem;
    const int tid = threadIdx.x, lane = tid & 31, wid = tid >> 5;
    const int wr = wid >> 2, wc = wid & 3;
    if (GATHER && tid < 128) s_tok[tid] = (m0 + tid < M) ? toks[m0 + tid] : 0;
    __syncthreads();

    // loader: one 64B row per thread, 4 swizzled 16B cp.asyncs per chunk
    int lrow, lbase;
    const __half* lsrc;
    bool aok = true;
    if (tid < 128) {
        lrow = tid; lbase = 0;
        aok = (m0 + tid) < M;
        const int ar = GATHER ? (aok ? s_tok[tid] : 0) : (aok ? m0 + tid : 0);
        lsrc = X + (size_t)ar * K;
    } else if (tid < 192) {
        lrow = tid - 128; lbase = 8192;
        lsrc = Wg + (size_t)(n0 + lrow) * K;
    } else {
        lrow = tid - 192; lbase = 12288;
        lsrc = Wu + (size_t)(n0 + lrow) * K;
    }
    const char* Lp = (const char*)lsrc;
    const int swzr = (lrow >> 1) & 3;
    const uint32_t sb = smem_u32(smem) + 512;
    const uint32_t dRow = sb + lbase + lrow * 64;
    const uint32_t sz = aok ? 16u : 0u;

    const int C = K >> 5;
    auto load = [&](int c, int buf) {
        const char* s = Lp + c * 64;
        const uint32_t d = dRow + buf * G1_STAGE;
        CP_ASYNC(d + ((0 ^ swzr) << 4), s,      sz);
        CP_ASYNC(d + ((1 ^ swzr) << 4), s + 16, sz);
        CP_ASYNC(d + ((2 ^ swzr) << 4), s + 32, sz);
        CP_ASYNC(d + ((3 ^ swzr) << 4), s + 48, sz);
    };

    // consumer ldmatrix lane geometry
    const int sub = lane >> 3, rsub = lane & 7;
    const int subk = sub >> 1, subm = (sub & 1) * 8;
    const int mA = wr * 64 + subm + rsub;
    const int swzA = (mA >> 1) & 3;
    const uint32_t aBase = sb + mA * 64;
    const uint32_t kofA[2] = { (uint32_t)(((0 + subk) ^ swzA) << 4),
                               (uint32_t)(((2 + subk) ^ swzA) << 4) };
    const int nB = wc * 16 + subm + rsub;
    const int swzB = (nB >> 1) & 3;
    const uint32_t gBase = sb + 8192 + nB * 64;
    const uint32_t kofB[2] = { (uint32_t)(((0 + subk) ^ swzB) << 4),
                               (uint32_t)(((2 + subk) ^ swzB) << 4) };

    float cg[4][2][4] = {}, cu[4][2][4] = {};
    #pragma unroll
    for (int s = 0; s < 3; s++) { if (s < C) load(s, s); CP_COMMIT(); }

    const int l4 = lane >> 2, lm = lane & 3;
    #pragma unroll 1
    for (int c = 0; c < C; c++) {
        CP_WAIT(2);
        __syncthreads();
        const uint32_t stg = (c & 3) * G1_STAGE;
        #pragma unroll
        for (int ks = 0; ks < 2; ks++) {
            uint32_t a[4][4];
            #pragma unroll
            for (int mi = 0; mi < 4; mi++)
                ldsm4(a[mi], aBase + stg + mi * 1024 + kofA[ks]);
            uint32_t g4[4], u4[4];
            ldsm4(g4, gBase + stg + kofB[ks]);
            ldsm4(u4, gBase + 4096 + stg + kofB[ks]);
            #pragma unroll
            for (int ni = 0; ni < 2; ni++) {
                uint32_t bg[2] = { g4[ni], g4[ni + 2] };
                uint32_t bu[2] = { u4[ni], u4[ni + 2] };
                #pragma unroll
                for (int mi = 0; mi < 4; mi++) {
                    mma16(cg[mi][ni], a[mi], bg);
                    mma16(cu[mi][ni], a[mi], bu);
                }
            }
        }
        const int nc = c + 3;
        if (nc < C) load(nc, nc & 3);
        CP_COMMIT();
    }
    // epilogue: silu(g)*u -> natural fp16 half2 stores
    #pragma unroll
    for (int mi = 0; mi < 4; mi++)
        #pragma unroll
        for (int h = 0; h < 2; h++) {
            const int r = m0 + wr * 64 + mi * 16 + l4 + h * 8;
            if (r >= M) continue;
            __half* hrow = Ho + (size_t)r * ldH + n0 + wc * 16 + 2 * lm;
            #pragma unroll
            for (int ni = 0; ni < 2; ni++) {
                const float v0 = silu(cg[mi][ni][2 * h + 0]) * cu[mi][ni][2 * h + 0];
                const float v1 = silu(cg[mi][ni][2 * h + 1]) * cu[mi][ni][2 * h + 1];
                *(uint32_t*)(hrow + ni * 8) = h2u(__floats2half2_rn(v0, v1));
            }
        }
}

// ---------------- GEMM2 fp16 ldmatrix: down --------------------------------
// Tile 128M x 128N, warp 64x32, Kc=32, 4-stage. Stage 16384B: A @0 | B @8192
#define G2_STAGE 16384
#define G2_SMEM  (1024 + 4 * G2_STAGE)
template <bool ROUTED>
__global__ void __launch_bounds__(256, 2)
gemm2_h(const __half* __restrict__ Hin_, const __half* __restrict__ Wd_,
        float* __restrict__ Out, int K) {
    const int e = blockIdx.z;
    int M; const __half *Hin, *Wd; const int* toks = nullptr; const float* wts = nullptr;
    if (ROUTED) {
        M = d_cnt[e];
        Hin = Hin_ + (size_t)e * NT * ID;
        Wd  = Wd_  + (size_t)e * HD * ID;
        toks = d_tok + e * NT; wts = d_wt + e * NT;
    } else {
        M = NT; Hin = Hin_; Wd = Wd_;
    }
    const int m0 = blockIdx.y * 128;
    if (m0 >= M) return;
    const int n0 = blockIdx.x * 128;

    extern __shared__ char smem[];
    int*   s_tok = (int*)smem;
    float* s_wt  = (float*)(smem + 512);
    const int tid = threadIdx.x, lane = tid & 31, wid = tid >> 5;
    const int wr = wid >> 2, wc = wid & 3;
    if (ROUTED && tid < 128) {
        const bool ok = m0 + tid < M;
        s_tok[tid] = ok ? toks[m0 + tid] : 0;
        s_wt [tid] = ok ? wts [m0 + tid] : 0.f;
    }
    __syncthreads();

    int lrow, lbase;
    const __half* lsrc;
    bool aok = true;
    if (tid < 128) {
        lrow = tid; lbase = 0;
        aok = (m0 + tid) < M;
        lsrc = Hin + (size_t)(aok ? m0 + tid : 0) * K;
    } else {
        lrow = tid - 128; lbase = 8192;
        lsrc = Wd + (size_t)(n0 + lrow) * K;
    }
    const char* Lp = (const char*)lsrc;
    const int swzr = (lrow >> 1) & 3;
    const uint32_t sb = smem_u32(smem) + 1024;
    const uint32_t dRow = sb + lbase + lrow * 64;
    const uint32_t sz = aok ? 16u : 0u;

    const int C = K >> 5;
    auto load = [&](int c, int buf) {
        const char* s = Lp + c * 64;
        const uint32_t d = dRow + buf * G2_STAGE;
        CP_ASYNC(d + ((0 ^ swzr) << 4), s,      sz);
        CP_ASYNC(d + ((1 ^ swzr) << 4), s + 16, sz);
        CP_ASYNC(d + ((2 ^ swzr) << 4), s + 32, sz);
        CP_ASYNC(d + ((3 ^ swzr) << 4), s + 48, sz);
    };

    const int sub = lane >> 3, rsub = lane & 7;
    const int subk = sub >> 1, subm = (sub & 1) * 8;
    const int mA = wr * 64 + subm + rsub;
    const int swzA = (mA >> 1) & 3;
    const uint32_t aBase = sb + mA * 64;
    const uint32_t kofA[2] = { (uint32_t)(((0 + subk) ^ swzA) << 4),
                               (uint32_t)(((2 + subk) ^ swzA) << 4) };
    const int nB = wc * 32 + subm + rsub;       // j=0 half; j=1 adds 16 rows
    const int swzB = (nB >> 1) & 3;             // invariant under +16
    const uint32_t bBase = sb + 8192 + nB * 64;
    const uint32_t kofB[2] = { (uint32_t)(((0 + subk) ^ swzB) << 4),
                               (uint32_t)(((2 + subk) ^ swzB) << 4) };

    float acc[4][4][4] = {};
    #pragma unroll
    for (int s = 0; s < 3; s++) { if (s < C) load(s, s); CP_COMMIT(); }

    const int l4 = lane >> 2, lm = lane & 3;
    #pragma unroll 1
    for (int c = 0; c < C; c++) {
        CP_WAIT(2);
        __syncthreads();
        const uint32_t stg = (c & 3) * G2_STAGE;
        #pragma unroll
        for (int ks = 0; ks < 2; ks++) {
            uint32_t a[4][4];
            #pragma unroll
            for (int mi = 0; mi < 4; mi++)
                ldsm4(a[mi], aBase + stg + mi * 1024 + kofA[ks]);
            #pragma unroll
            for (int j = 0; j < 2; j++) {
                uint32_t b4[4];
                ldsm4(b4, bBase + stg + j * 1024 + kofB[ks]);
                #pragma unroll
                for (int nj = 0; nj < 2; nj++) {
                    uint32_t b[2] = { b4[nj], b4[nj + 2] };
                    #pragma unroll
                    for (int mi = 0; mi < 4; mi++)
                        mma16(acc[mi][j * 2 + nj], a[mi], b);
                }
            }
        }
        const int nc = c + 3;
        if (nc < C) load(nc, nc & 3);
        CP_COMMIT();
    }
    #pragma unroll
    for (int mi = 0; mi < 4; mi++) {
        const int rl0 = wr * 64 + mi * 16 + l4;
        #pragma unroll
        for (int ni = 0; ni < 4; ni++) {
            const int cc = n0 + wc * 32 + ni * 8 + 2 * lm;
            #pragma unroll
            for (int h = 0; h < 2; h++) {
                const int rl = rl0 + h * 8;
                if (m0 + rl >= M) continue;
                const float v0 = acc[mi][ni][2 * h + 0];
                const float v1 = acc[mi][ni][2 * h + 1];
                if (ROUTED) {
                    const float w = s_wt[rl];
                    float* o = Out + (size_t)s_tok[rl] * HD + cc;
                    atomicAdd(o + 0, w * v0);
                    atomicAdd(o + 1, w * v1);
                } else {
                    float2 v = { v0, v1 };
                    *(float2*)(Out + (size_t)(m0 + rl) * HD + cc) = v;
                }
            }
        }
    }
}

// ---------------- launch ----------------
extern "C" void kernel_launch(void* const* d_in, const int* in_sizes, int n_in,
                              void* d_out, int out_size) {
    const float* x       = (const float*)d_in[0];
    const float* gate_w  = (const float*)d_in[1];
    const float* gate_b  = (const float*)d_in[2];
    const float* w_gate  = (const float*)d_in[3];
    const float* w_up    = (const float*)d_in[4];
    const float* w_down  = (const float*)d_in[5];
    const float* sw_gate = (const float*)d_in[6];
    const float* sw_up   = (const float*)d_in[7];
    const float* sw_down = (const float*)d_in[8];
    float* out = (float*)d_out;

    __half *wg16, *wu16, *wd16, *sg16, *su16, *sd16, *xh, *hr, *hs;
    cudaGetSymbolAddress((void**)&wg16, w_g16);
    cudaGetSymbolAddress((void**)&wu16, w_u16);
    cudaGetSymbolAddress((void**)&wd16, w_d16);
    cudaGetSymbolAddress((void**)&sg16, sw_g16);
    cudaGetSymbolAddress((void**)&su16, sw_u16);
    cudaGetSymbolAddress((void**)&sd16, sw_d16);
    cudaGetSymbolAddress((void**)&xh,   x16);
    cudaGetSymbolAddress((void**)&hr,   h_r16);
    cudaGetSymbolAddress((void**)&hs,   h_s16);

    cudaFuncSetAttribute(gemm1_h<true>,  cudaFuncAttributeMaxDynamicSharedMemorySize, G1_SMEM);
    cudaFuncSetAttribute(gemm1_h<false>, cudaFuncAttributeMaxDynamicSharedMemorySize, G1_SMEM);
    cudaFuncSetAttribute(gemm2_h<true>,  cudaFuncAttributeMaxDynamicSharedMemorySize, G2_SMEM);
    cudaFuncSetAttribute(gemm2_h<false>, cudaFuncAttributeMaxDynamicSharedMemorySize, G2_SMEM);

    init_kernel<<<1, 32>>>();
    conv16<<<11264, 256>>>((const float4*)w_gate,  (uint4*)wg16);
    conv16<<<11264, 256>>>((const float4*)w_up,    (uint4*)wu16);
    conv16<<<11264, 256>>>((const float4*)w_down,  (uint4*)wd16);
    conv16<<<1408,  256>>>((const float4*)sw_gate, (uint4*)sg16);
    conv16<<<1408,  256>>>((const float4*)sw_up,   (uint4*)su16);
    conv16<<<1408,  256>>>((const float4*)sw_down, (uint4*)sd16);
    conv16<<<512,   256>>>((const float4*)x,       (uint4*)xh);
    gate_kernel<<<NT, 512>>>(x, gate_w, gate_b);

    // routed gate/up + silu
    gemm1_h<true><<<dim3(ID / 64, NT / 128, NE), 256, G1_SMEM>>>(
        xh, wg16, wu16, hr, ID, HD);
    // shared gate/up + silu
    gemm1_h<false><<<dim3(SID / 64, NT / 128, 1), 256, G1_SMEM>>>(
        xh, sg16, su16, hs, SID, HD);
    // shared down: plain stores initialize d_out fully
    gemm2_h<false><<<dim3(HD / 128, NT / 128, 1), 256, G2_SMEM>>>(
        hs, sd16, out, SID);
    // routed down: atomic scatter-add
    gemm2_h<true><<<dim3(HD / 128, NT / 128, NE), 256, G2_SMEM>>>(
        hr, wd16, out, ID);
}

// round 11
// speedup vs baseline: 1.3556x; 1.2757x over previous
#include <cuda_runtime.h>
#include <cuda_fp16.h>
#include <math.h>
#include <cstdint>

#define HD 2048
#define ID 1408
#define NE 16
#define TK 4
#define NT 1024
#define SID 2816
#define RSCALE 2.5f

// ---------------- scratch ----------------
__device__ int    d_cnt[NE];
__device__ int    d_tok[NE * NT];
__device__ float  d_wt [NE * NT];
// fp16 pair-permuted copies (K-groups of 16 stored as [p0,p4,p1,p5,p2,p6,p3,p7])
__device__ __half w_g16[NE * ID * HD];
__device__ __half w_u16[NE * ID * HD];
__device__ __half w_d16[NE * HD * ID];
__device__ __half sw_g16[SID * HD];
__device__ __half sw_u16[SID * HD];
__device__ __half sw_d16[HD * SID];
__device__ __half x16  [NT * HD];
__device__ __half h_r16[NE * NT * ID];
__device__ __half h_s16[NT * SID];

// ---------------- PTX helpers ----------------
__device__ __forceinline__ uint32_t smem_u32(const void* p) {
    uint32_t a;
    asm("{ .reg .u64 t; cvta.to.shared.u64 t, %1; cvt.u32.u64 %0, t; }"
        : "=r"(a) : "l"(p));
    return a;
}
#define CP_ASYNC(dst, src, sz) \
    asm volatile("cp.async.cg.shared.global [%0], [%1], 16, %2;" \
                 :: "r"(dst), "l"(src), "r"(sz) : "memory")
#define CP_COMMIT() asm volatile("cp.async.commit_group;" ::: "memory")
#define CP_WAIT(n)  asm volatile("cp.async.wait_group %0;" :: "n"(n) : "memory")

__device__ __forceinline__ void mma16(float* c, const uint32_t* a, const uint32_t* b) {
    asm volatile(
        "mma.sync.aligned.m16n8k16.row.col.f32.f16.f16.f32 "
        "{%0,%1,%2,%3}, {%4,%5,%6,%7}, {%8,%9}, {%0,%1,%2,%3};"
        : "+f"(c[0]), "+f"(c[1]), "+f"(c[2]), "+f"(c[3])
        : "r"(a[0]), "r"(a[1]), "r"(a[2]), "r"(a[3]), "r"(b[0]), "r"(b[1]));
}
__device__ __forceinline__ float silu(float g) { return g / (1.f + __expf(-g)); }
__device__ __forceinline__ uint32_t h2u(__half2 h) {
    uint32_t u; *(__half2*)&u = h; return u;
}

// smem rows: 64B data (32 fp16, permuted) + 32B pad = 96B (12 uint2)
#define ROWB 96
#define ROWU2 12

// ---------------- init / memset / converts ----------------
__global__ void init_kernel() {
    if (threadIdx.x < NE) d_cnt[threadIdx.x] = 0;
}
__global__ void zero_out(float4* out) {
    out[blockIdx.x * 256 + threadIdx.x] = make_float4(0.f, 0.f, 0.f, 0.f);
}
// fp32 -> fp16, permuting each flat 16-element group to pair order
__global__ void conv_perm(const float4* __restrict__ src, uint4* __restrict__ dst) {
    const size_t t = (size_t)blockIdx.x * 256 + threadIdx.x;
    float4 f0 = src[4 * t], f1 = src[4 * t + 1], f2 = src[4 * t + 2], f3 = src[4 * t + 3];
    const float f[16] = { f0.x, f0.y, f0.z, f0.w, f1.x, f1.y, f1.z, f1.w,
                          f2.x, f2.y, f2.z, f2.w, f3.x, f3.y, f3.z, f3.w };
    uint32_t h[8];
    #pragma unroll
    for (int s = 0; s < 8; s++) {
        const int j = (s & 1) ? ((s >> 1) + 4) : (s >> 1);
        h[s] = h2u(__floats2half2_rn(f[2 * j], f[2 * j + 1]));
    }
    dst[2 * t]     = make_uint4(h[0], h[1], h[2], h[3]);
    dst[2 * t + 1] = make_uint4(h[4], h[5], h[6], h[7]);
}

// ---------------- gate (raw fp32 x) ----------------
__global__ void gate_kernel(const float* __restrict__ x,
                            const float* __restrict__ gw,
                            const float* __restrict__ gb) {
    const int t = blockIdx.x;
    __shared__ float s_sc[NE];
    const int wid = threadIdx.x >> 5;
    const int lane = threadIdx.x & 31;
    const float* xr = x + (size_t)t * HD;
    const float* wr = gw + (size_t)wid * HD;
    float acc = 0.f;
    for (int k = lane; k < HD; k += 32) acc += xr[k] * wr[k];
    #pragma unroll
    for (int o = 16; o; o >>= 1) acc += __shfl_xor_sync(0xffffffffu, acc, o);
    if (lane == 0) s_sc[wid] = 1.f / (1.f + expf(-acc)) + gb[wid];
    __syncthreads();
    if (threadIdx.x != 0) return;

    float sc[NE];
    #pragma unroll
    for (int e = 0; e < NE; e++) sc[e] = s_sc[e];
    float gs[4];
    #pragma unroll
    for (int g = 0; g < 4; g++) {
        float m = sc[g * 4];
        #pragma unroll
        for (int j = 1; j < 4; j++) m = fmaxf(m, sc[g * 4 + j]);
        gs[g] = m;
    }
    int g0 = 0;
    for (int g = 1; g < 4; g++) if (gs[g] > gs[g0]) g0 = g;
    int g1 = -1;
    for (int g = 0; g < 4; g++) {
        if (g == g0) continue;
        if (g1 < 0 || gs[g] > gs[g1]) g1 = g;
    }
    float masked[NE];
    #pragma unroll
    for (int e = 0; e < NE; e++) {
        int g = e >> 2;
        masked[e] = (g == g0 || g == g1) ? sc[e] : 0.f;
    }
    int idx[TK]; float w[TK]; bool used[NE];
    #pragma unroll
    for (int e = 0; e < NE; e++) used[e] = false;
    float wsum = 0.f;
    for (int k = 0; k < TK; k++) {
        int best = -1;
        for (int e = 0; e < NE; e++) {
            if (used[e]) continue;
            if (best < 0 || masked[e] > masked[best]) best = e;
        }
        used[best] = true;
        idx[k] = best; w[k] = masked[best]; wsum += masked[best];
    }
    const float inv = 1.f / (wsum + 1e-6f);
    for (int k = 0; k < TK; k++) {
        int e = idx[k];
        int pos = atomicAdd(&d_cnt[e], 1);
        d_tok[e * NT + pos] = t;
        d_wt [e * NT + pos] = w[k] * inv * RSCALE;
    }
}

// ---------------- GEMM1 fp16 merged: routed z<16, shared z==16 -------------
// Tile 128M x 64N dual, Kc=32, 3-stage cp.async (R8 mainloop, unchanged).
// Stage: A 128x96B @0 | G 64x96B @12288 | U @18432 ; stride 24576
#define G1_STAGE 24576
#define G1_SMEM  (512 + 3 * G1_STAGE)
__global__ void __launch_bounds__(256, 2)
gemm1_h(const __half* __restrict__ X,
        const __half* __restrict__ Wg_r, const __half* __restrict__ Wu_r,
        const __half* __restrict__ Wg_s, const __half* __restrict__ Wu_s,
        __half* __restrict__ Hr, __half* __restrict__ Hs) {
    const int e = blockIdx.z;
    const bool SH = (e == NE);
    int M, ldH, ntile;
    const __half *Wg, *Wu; __half* Ho;
    if (SH) {
        M = NT; ldH = SID; ntile = SID / 64;
        Wg = Wg_s; Wu = Wu_s; Ho = Hs;
    } else {
        M = d_cnt[e]; ldH = ID; ntile = ID / 64;
        Wg = Wg_r + (size_t)e * ID * HD;
        Wu = Wu_r + (size_t)e * ID * HD;
        Ho = Hr + (size_t)e * NT * ID;
    }
    if ((int)blockIdx.x >= ntile) return;
    const int m0 = blockIdx.y * 128;
    if (m0 >= M) return;
    const int n0 = blockIdx.x * 64;
    const int K = HD;

    extern __shared__ char smem[];
    int* s_tok = (int*)smem;
    const int tid = threadIdx.x, lane = tid & 31, wid = tid >> 5;
    const int wr = wid >> 2, wc = wid & 3;
    if (!SH && tid < 128) s_tok[tid] = (m0 + tid < M) ? d_tok[e * NT + m0 + tid] : 0;
    __syncthreads();

    // loader: A row tid>>1 (2 segs), G row tid>>2 (1 seg), U row tid>>2 (1 seg)
    const int rA = tid >> 1, sA = (tid & 1) * 2;
    const int rW = tid >> 2, sW = tid & 3;
    const bool aok = (m0 + rA) < M;
    const int ar = SH ? (aok ? m0 + rA : 0) : (aok ? s_tok[rA] : 0);
    const char* Ap = (const char*)(X + (size_t)ar * K);
    const char* Gp = (const char*)(Wg + (size_t)(n0 + rW) * K);
    const char* Up = (const char*)(Wu + (size_t)(n0 + rW) * K);
    const uint32_t sb = smem_u32(smem) + 512;
    const uint32_t dA = sb + rA * ROWB + sA * 16;
    const uint32_t dG = sb + 12288 + rW * ROWB + sW * 16;
    const uint32_t dU = sb + 18432 + rW * ROWB + sW * 16;
    const uint32_t szA = aok ? 16u : 0u;

    const int C = K >> 5;
    auto load = [&](int c, int buf) {
        const int off = c * 64;
        const uint32_t b = buf * G1_STAGE;
        CP_ASYNC(dA + b,      Ap + off + sA * 16,      szA);
        CP_ASYNC(dA + b + 16, Ap + off + sA * 16 + 16, szA);
        CP_ASYNC(dG + b,      Gp + off + sW * 16, 16);
        CP_ASYNC(dU + b,      Up + off + sW * 16, 16);
    };

    float cg[4][2][4] = {}, cu[4][2][4] = {};
    #pragma unroll
    for (int s = 0; s < 2; s++) { if (s < C) load(s, s); CP_COMMIT(); }

    const int l4 = lane >> 2, lm = lane & 3;
    const int a_off = (wr * 64 + l4) * ROWU2 + lm;
    const int g_off = 1536 + (wc * 16 + l4) * ROWU2 + lm;
    #pragma unroll 1
    for (int c = 0; c < C; c++) {
        CP_WAIT(1);
        __syncthreads();
        const int nc = c + 2;
        if (nc < C) load(nc, nc % 3);
        CP_COMMIT();
        const uint2* S = (const uint2*)(smem + 512 + (c % 3) * G1_STAGE);
        #pragma unroll
        for (int ks = 0; ks < 2; ks++) {
            uint32_t a[4][4];
            #pragma unroll
            for (int mi = 0; mi < 4; mi++) {
                const uint2 p = S[a_off + mi * (16 * ROWU2) + ks * 4];
                const uint2 q = S[a_off + mi * (16 * ROWU2) + 8 * ROWU2 + ks * 4];
                a[mi][0] = p.x; a[mi][1] = q.x; a[mi][2] = p.y; a[mi][3] = q.y;
            }
            #pragma unroll
            for (int ni = 0; ni < 2; ni++) {
                const uint2 vg = S[g_off + ni * (8 * ROWU2) + ks * 4];
                const uint2 vu = S[g_off + 768 + ni * (8 * ROWU2) + ks * 4];
                uint32_t bg[2] = { vg.x, vg.y };
                uint32_t bu[2] = { vu.x, vu.y };
                #pragma unroll
                for (int mi = 0; mi < 4; mi++) {
                    mma16(cg[mi][ni], a[mi], bg);
                    mma16(cu[mi][ni], a[mi], bu);
                }
            }
        }
    }
    // epilogue: silu(g)*u -> fp16 pair-permuted
    #pragma unroll
    for (int mi = 0; mi < 4; mi++)
        #pragma unroll
        for (int h = 0; h < 2; h++) {
            const int r = m0 + wr * 64 + mi * 16 + l4 + h * 8;
            if (r >= M) continue;
            const float v0 = silu(cg[mi][0][2 * h + 0]) * cu[mi][0][2 * h + 0];
            const float v1 = silu(cg[mi][0][2 * h + 1]) * cu[mi][0][2 * h + 1];
            const float v2 = silu(cg[mi][1][2 * h + 0]) * cu[mi][1][2 * h + 0];
            const float v3 = silu(cg[mi][1][2 * h + 1]) * cu[mi][1][2 * h + 1];
            uint2 val = { h2u(__floats2half2_rn(v0, v1)), h2u(__floats2half2_rn(v2, v3)) };
            ((uint2*)(Ho + (size_t)r * ldH + n0 + wc * 16))[lm] = val;
        }
}

// ---------------- GEMM2 fp16 merged: routed z<16, shared z==16 -------------
// Tile 128M x 128N, Kc=32, 4-stage (R8 mainloop). Atomic scatter for both.
#define G2_STAGE 24576
#define G2_SMEM  (1024 + 4 * G2_STAGE)
__global__ void __launch_bounds__(256, 2)
gemm2_h(const __half* __restrict__ Hr, const __half* __restrict__ Wd_r,
        const __half* __restrict__ Hs, const __half* __restrict__ Wd_s,
        float* __restrict__ Out) {
    const int e = blockIdx.z;
    const bool SH = (e == NE);
    int M, K;
    const __half *Hin, *Wd;
    if (SH) {
        M = NT; K = SID; Hin = Hs; Wd = Wd_s;
    } else {
        M = d_cnt[e]; K = ID;
        Hin = Hr + (size_t)e * NT * ID;
        Wd  = Wd_r + (size_t)e * HD * ID;
    }
    const int m0 = blockIdx.y * 128;
    if (m0 >= M) return;
    const int n0 = blockIdx.x * 128;

    extern __shared__ char smem[];
    int*   s_tok = (int*)smem;
    float* s_wt  = (float*)(smem + 512);
    const int tid = threadIdx.x, lane = tid & 31, wid = tid >> 5;
    const int wr = wid >> 2, wc = wid & 3;
    if (tid < 128) {
        const bool ok = m0 + tid < M;
        if (SH) { s_tok[tid] = ok ? m0 + tid : 0; s_wt[tid] = 1.f; }
        else {
            s_tok[tid] = ok ? d_tok[e * NT + m0 + tid] : 0;
            s_wt [tid] = ok ? d_wt [e * NT + m0 + tid] : 0.f;
        }
    }
    __syncthreads();

    const int rA = tid >> 1, sA = (tid & 1) * 2;
    const bool aok = (m0 + rA) < M;
    const char* Ap = (const char*)(Hin + (size_t)(aok ? m0 + rA : 0) * K);
    const char* Bp = (const char*)(Wd + (size_t)(n0 + rA) * K);
    const uint32_t sb = smem_u32(smem) + 1024;
    const uint32_t dA = sb + rA * ROWB + sA * 16;
    const uint32_t dB = sb + 12288 + rA * ROWB + sA * 16;
    const uint32_t szA = aok ? 16u : 0u;

    const int C = K >> 5;
    auto load = [&](int c, int buf) {
        const int off = c * 64;
        const uint32_t b = buf * G2_STAGE;
        CP_ASYNC(dA + b,      Ap + off + sA * 16,      szA);
        CP_ASYNC(dA + b + 16, Ap + off + sA * 16 + 16, szA);
        CP_ASYNC(dB + b,      Bp + off + sA * 16,      16);
        CP_ASYNC(dB + b + 16, Bp + off + sA * 16 + 16, 16);
    };

    float acc[4][4][4] = {};
    #pragma unroll
    for (int s = 0; s < 3; s++) { if (s < C) load(s, s); CP_COMMIT(); }

    const int l4 = lane >> 2, lm = lane & 3;
    const int a_off = (wr * 64 + l4) * ROWU2 + lm;
    const int b_off = 1536 + (wc * 32 + l4) * ROWU2 + lm;
    #pragma unroll 1
    for (int c = 0; c < C; c++) {
        CP_WAIT(2);
        __syncthreads();
        const int nc = c + 3;
        if (nc < C) load(nc, nc & 3);
        CP_COMMIT();
        const uint2* S = (const uint2*)(smem + 1024 + (c & 3) * G2_STAGE);
        #pragma unroll
        for (int ks = 0; ks < 2; ks++) {
            uint32_t a[4][4];
            #pragma unroll
            for (int mi = 0; mi < 4; mi++) {
                const uint2 p = S[a_off + mi * (16 * ROWU2) + ks * 4];
                const uint2 q = S[a_off + mi * (16 * ROWU2) + 8 * ROWU2 + ks * 4];
                a[mi][0] = p.x; a[mi][1] = q.x; a[mi][2] = p.y; a[mi][3] = q.y;
            }
            #pragma unroll
            for (int ni = 0; ni < 4; ni++) {
                const uint2 vb = S[b_off + ni * (8 * ROWU2) + ks * 4];
                uint32_t b[2] = { vb.x, vb.y };
                #pragma unroll
                for (int mi = 0; mi < 4; mi++)
                    mma16(acc[mi][ni], a[mi], b);
            }
        }
    }
    #pragma unroll
    for (int mi = 0; mi < 4; mi++) {
        const int rl0 = wr * 64 + mi * 16 + l4;
        #pragma unroll
        for (int ni = 0; ni < 4; ni++) {
            const int cc = n0 + wc * 32 + ni * 8 + 2 * lm;
            #pragma unroll
            for (int h = 0; h < 2; h++) {
                const int rl = rl0 + h * 8;
                if (m0 + rl >= M) continue;
                const float w = s_wt[rl];
                float* o = Out + (size_t)s_tok[rl] * HD + cc;
                atomicAdd(o + 0, w * acc[mi][ni][2 * h + 0]);
                atomicAdd(o + 1, w * acc[mi][ni][2 * h + 1]);
            }
        }
    }
}

// ---------------- launch ----------------
extern "C" void kernel_launch(void* const* d_in, const int* in_sizes, int n_in,
                              void* d_out, int out_size) {
    const float* x       = (const float*)d_in[0];
    const float* gate_w  = (const float*)d_in[1];
    const float* gate_b  = (const float*)d_in[2];
    const float* w_gate  = (const float*)d_in[3];
    const float* w_up    = (const float*)d_in[4];
    const float* w_down  = (const float*)d_in[5];
    const float* sw_gate = (const float*)d_in[6];
    const float* sw_up   = (const float*)d_in[7];
    const float* sw_down = (const float*)d_in[8];
    float* out = (float*)d_out;

    __half *wg16, *wu16, *wd16, *sg16, *su16, *sd16, *xh, *hr, *hs;
    cudaGetSymbolAddress((void**)&wg16, w_g16);
    cudaGetSymbolAddress((void**)&wu16, w_u16);
    cudaGetSymbolAddress((void**)&wd16, w_d16);
    cudaGetSymbolAddress((void**)&sg16, sw_g16);
    cudaGetSymbolAddress((void**)&su16, sw_u16);
    cudaGetSymbolAddress((void**)&sd16, sw_d16);
    cudaGetSymbolAddress((void**)&xh,   x16);
    cudaGetSymbolAddress((void**)&hr,   h_r16);
    cudaGetSymbolAddress((void**)&hs,   h_s16);

    cudaFuncSetAttribute(gemm1_h, cudaFuncAttributeMaxDynamicSharedMemorySize, G1_SMEM);
    cudaFuncSetAttribute(gemm2_h, cudaFuncAttributeMaxDynamicSharedMemorySize, G2_SMEM);

    init_kernel<<<1, 32>>>();
    zero_out<<<(NT * HD) / 1024, 256>>>((float4*)out);
    conv_perm<<<11264, 256>>>((const float4*)w_gate,  (uint4*)wg16);
    conv_perm<<<11264, 256>>>((const float4*)w_up,    (uint4*)wu16);
    conv_perm<<<11264, 256>>>((const float4*)w_down,  (uint4*)wd16);
    conv_perm<<<1408,  256>>>((const float4*)sw_gate, (uint4*)sg16);
    conv_perm<<<1408,  256>>>((const float4*)sw_up,   (uint4*)su16);
    conv_perm<<<1408,  256>>>((const float4*)sw_down, (uint4*)sd16);
    conv_perm<<<512,   256>>>((const float4*)x,       (uint4*)xh);
    gate_kernel<<<NT, 512>>>(x, gate_w, gate_b);

    // merged gate/up + silu: z 0..15 routed (22 n-tiles used), z 16 shared (44)
    gemm1_h<<<dim3(SID / 64, NT / 128, NE + 1), 256, G1_SMEM>>>(
        xh, wg16, wu16, sg16, su16, hr, hs);
    // merged down: z 0..15 routed (K=ID), z 16 shared (K=SID); atomics into zeroed out
    gemm2_h<<<dim3(HD / 128, NT / 128, NE + 1), 256, G2_SMEM>>>(
        hr, wd16, hs, sd16, out);
}

// round 12
// speedup vs baseline: 1.3676x; 1.0089x over previous
#include <cuda_runtime.h>
#include <cuda_fp16.h>
#include <math.h>
#include <cstdint>

#define HD 2048
#define ID 1408
#define NE 16
#define TK 4
#define NT 1024
#define SID 2816
#define RSCALE 2.5f

// ---------------- scratch ----------------
__device__ int    d_cnt[NE];
__device__ int    d_tok[NE * NT];
__device__ float  d_wt [NE * NT];
// fp16 pair-permuted copies (K-groups of 16 stored as [p0,p4,p1,p5,p2,p6,p3,p7])
__device__ __half w_g16[NE * ID * HD];
__device__ __half w_u16[NE * ID * HD];
__device__ __half w_d16[NE * HD * ID];
__device__ __half sw_g16[SID * HD];
__device__ __half sw_u16[SID * HD];
__device__ __half sw_d16[HD * SID];
__device__ __half x16  [NT * HD];
__device__ __half h_r16[NE * NT * ID];
__device__ __half h_s16[NT * SID];

// ---------------- PTX helpers ----------------
__device__ __forceinline__ uint32_t smem_u32(const void* p) {
    uint32_t a;
    asm("{ .reg .u64 t; cvta.to.shared.u64 t, %1; cvt.u32.u64 %0, t; }"
        : "=r"(a) : "l"(p));
    return a;
}
#define CP_ASYNC(dst, src, sz) \
    asm volatile("cp.async.cg.shared.global [%0], [%1], 16, %2;" \
                 :: "r"(dst), "l"(src), "r"(sz) : "memory")
#define CP_COMMIT() asm volatile("cp.async.commit_group;" ::: "memory")
#define CP_WAIT(n)  asm volatile("cp.async.wait_group %0;" :: "n"(n) : "memory")

__device__ __forceinline__ void mma16(float* c, const uint32_t* a, const uint32_t* b) {
    asm volatile(
        "mma.sync.aligned.m16n8k16.row.col.f32.f16.f16.f32 "
        "{%0,%1,%2,%3}, {%4,%5,%6,%7}, {%8,%9}, {%0,%1,%2,%3};"
        : "+f"(c[0]), "+f"(c[1]), "+f"(c[2]), "+f"(c[3])
        : "r"(a[0]), "r"(a[1]), "r"(a[2]), "r"(a[3]), "r"(b[0]), "r"(b[1]));
}
__device__ __forceinline__ float silu(float g) { return g / (1.f + __expf(-g)); }
__device__ __forceinline__ uint32_t h2u(__half2 h) {
    uint32_t u; *(__half2*)&u = h; return u;
}

// smem rows: 64B data (32 fp16, permuted) + 32B pad = 96B (12 uint2)
#define ROWB 96
#define ROWU2 12

// ---------------- init / memset ----------------
__global__ void init_kernel() {
    if (threadIdx.x < NE) d_cnt[threadIdx.x] = 0;
}
__global__ void zero_out(float4* out) {
    out[blockIdx.x * 256 + threadIdx.x] = make_float4(0.f, 0.f, 0.f, 0.f);
}

// ---------------- single merged conversion kernel -------------------------
// unit = 16 fp32 elements -> 16 fp16 pair-permuted
#define U_W ((size_t)NE * ID * HD / 16)   // 2883584 per routed weight tensor
#define U_S ((size_t)SID * HD / 16)       // 360448 per shared weight tensor
#define U_X ((size_t)NT * HD / 16)        // 131072
#define U_TOTAL (3 * U_W + 3 * U_S + U_X) // 9863168
#define CONV_BLOCKS ((int)(U_TOTAL / 256))

__device__ __forceinline__ void conv_unit(const float4* __restrict__ s,
                                          uint4* __restrict__ d, size_t t) {
    float4 f0 = s[4 * t], f1 = s[4 * t + 1], f2 = s[4 * t + 2], f3 = s[4 * t + 3];
    const float f[16] = { f0.x, f0.y, f0.z, f0.w, f1.x, f1.y, f1.z, f1.w,
                          f2.x, f2.y, f2.z, f2.w, f3.x, f3.y, f3.z, f3.w };
    uint32_t h[8];
    #pragma unroll
    for (int q = 0; q < 8; q++) {
        const int j = (q & 1) ? ((q >> 1) + 4) : (q >> 1);
        h[q] = h2u(__floats2half2_rn(f[2 * j], f[2 * j + 1]));
    }
    d[2 * t]     = make_uint4(h[0], h[1], h[2], h[3]);
    d[2 * t + 1] = make_uint4(h[4], h[5], h[6], h[7]);
}

__global__ void conv_all(const float4* wg, const float4* wu, const float4* wd,
                         const float4* sg, const float4* su, const float4* sd,
                         const float4* xx,
                         uint4* owg, uint4* owu, uint4* owd,
                         uint4* osg, uint4* osu, uint4* osd, uint4* oxx) {
    size_t u = (size_t)blockIdx.x * 256 + threadIdx.x;
    if (u < U_W)                 { conv_unit(wg, owg, u);                 return; }
    u -= U_W;
    if (u < U_W)                 { conv_unit(wu, owu, u);                 return; }
    u -= U_W;
    if (u < U_W)                 { conv_unit(wd, owd, u);                 return; }
    u -= U_W;
    if (u < U_S)                 { conv_unit(sg, osg, u);                 return; }
    u -= U_S;
    if (u < U_S)                 { conv_unit(su, osu, u);                 return; }
    u -= U_S;
    if (u < U_S)                 { conv_unit(sd, osd, u);                 return; }
    u -= U_S;
    conv_unit(xx, oxx, u);
}

// ---------------- gate (raw fp32 x, float4 vectorized) ----------------
__global__ void gate_kernel(const float* __restrict__ x,
                            const float* __restrict__ gw,
                            const float* __restrict__ gb) {
    const int t = blockIdx.x;
    __shared__ float s_sc[NE];
    const int wid = threadIdx.x >> 5;
    const int lane = threadIdx.x & 31;
    const float4* xr = (const float4*)(x + (size_t)t * HD);
    const float4* wr = (const float4*)(gw + (size_t)wid * HD);
    float acc = 0.f;
    #pragma unroll 4
    for (int k = lane; k < HD / 4; k += 32) {
        float4 a = xr[k], b = wr[k];
        acc += a.x * b.x + a.y * b.y + a.z * b.z + a.w * b.w;
    }
    #pragma unroll
    for (int o = 16; o; o >>= 1) acc += __shfl_xor_sync(0xffffffffu, acc, o);
    if (lane == 0) s_sc[wid] = 1.f / (1.f + expf(-acc)) + gb[wid];
    __syncthreads();
    if (threadIdx.x != 0) return;

    float sc[NE];
    #pragma unroll
    for (int e = 0; e < NE; e++) sc[e] = s_sc[e];
    float gs[4];
    #pragma unroll
    for (int g = 0; g < 4; g++) {
        float m = sc[g * 4];
        #pragma unroll
        for (int j = 1; j < 4; j++) m = fmaxf(m, sc[g * 4 + j]);
        gs[g] = m;
    }
    int g0 = 0;
    for (int g = 1; g < 4; g++) if (gs[g] > gs[g0]) g0 = g;
    int g1 = -1;
    for (int g = 0; g < 4; g++) {
        if (g == g0) continue;
        if (g1 < 0 || gs[g] > gs[g1]) g1 = g;
    }
    float masked[NE];
    #pragma unroll
    for (int e = 0; e < NE; e++) {
        int g = e >> 2;
        masked[e] = (g == g0 || g == g1) ? sc[e] : 0.f;
    }
    int idx[TK]; float w[TK]; bool used[NE];
    #pragma unroll
    for (int e = 0; e < NE; e++) used[e] = false;
    float wsum = 0.f;
    for (int k = 0; k < TK; k++) {
        int best = -1;
        for (int e = 0; e < NE; e++) {
            if (used[e]) continue;
            if (best < 0 || masked[e] > masked[best]) best = e;
        }
        used[best] = true;
        idx[k] = best; w[k] = masked[best]; wsum += masked[best];
    }
    const float inv = 1.f / (wsum + 1e-6f);
    for (int k = 0; k < TK; k++) {
        int e = idx[k];
        int pos = atomicAdd(&d_cnt[e], 1);
        d_tok[e * NT + pos] = t;
        d_wt [e * NT + pos] = w[k] * inv * RSCALE;
    }
}

// ---------------- GEMM1 fp16 merged: routed z<16, shared z==16 -------------
// Tile 128M x 64N dual, Kc=32, 4-stage cp.async.
// Stage: A 128x96B @0 | G 64x96B @12288 | U @18432 ; stride 24576
#define G1_STAGE 24576
#define G1_SMEM  (512 + 4 * G1_STAGE)
__global__ void __launch_bounds__(256, 2)
gemm1_h(const __half* __restrict__ X,
        const __half* __restrict__ Wg_r, const __half* __restrict__ Wu_r,
        const __half* __restrict__ Wg_s, const __half* __restrict__ Wu_s,
        __half* __restrict__ Hr, __half* __restrict__ Hs) {
    const int e = blockIdx.z;
    const bool SH = (e == NE);
    int M, ldH, ntile;
    const __half *Wg, *Wu; __half* Ho;
    if (SH) {
        M = NT; ldH = SID; ntile = SID / 64;
        Wg = Wg_s; Wu = Wu_s; Ho = Hs;
    } else {
        M = d_cnt[e]; ldH = ID; ntile = ID / 64;
        Wg = Wg_r + (size_t)e * ID * HD;
        Wu = Wu_r + (size_t)e * ID * HD;
        Ho = Hr + (size_t)e * NT * ID;
    }
    if ((int)blockIdx.x >= ntile) return;
    const int m0 = blockIdx.y * 128;
    if (m0 >= M) return;
    const int n0 = blockIdx.x * 64;
    const int K = HD;

    extern __shared__ char smem[];
    int* s_tok = (int*)smem;
    const int tid = threadIdx.x, lane = tid & 31, wid = tid >> 5;
    const int wr = wid >> 2, wc = wid & 3;
    if (!SH && tid < 128) s_tok[tid] = (m0 + tid < M) ? d_tok[e * NT + m0 + tid] : 0;
    __syncthreads();

    const int rA = tid >> 1, sA = (tid & 1) * 2;
    const int rW = tid >> 2, sW = tid & 3;
    const bool aok = (m0 + rA) < M;
    const int ar = SH ? (aok ? m0 + rA : 0) : (aok ? s_tok[rA] : 0);
    const char* Ap = (const char*)(X + (size_t)ar * K);
    const char* Gp = (const char*)(Wg + (size_t)(n0 + rW) * K);
    const char* Up = (const char*)(Wu + (size_t)(n0 + rW) * K);
    const uint32_t sb = smem_u32(smem) + 512;
    const uint32_t dA = sb + rA * ROWB + sA * 16;
    const uint32_t dG = sb + 12288 + rW * ROWB + sW * 16;
    const uint32_t dU = sb + 18432 + rW * ROWB + sW * 16;
    const uint32_t szA = aok ? 16u : 0u;

    const int C = K >> 5;
    auto load = [&](int c, int buf) {
        const int off = c * 64;
        const uint32_t b = buf * G1_STAGE;
        CP_ASYNC(dA + b,      Ap + off + sA * 16,      szA);
        CP_ASYNC(dA + b + 16, Ap + off + sA * 16 + 16, szA);
        CP_ASYNC(dG + b,      Gp + off + sW * 16, 16);
        CP_ASYNC(dU + b,      Up + off + sW * 16, 16);
    };

    float cg[4][2][4] = {}, cu[4][2][4] = {};
    #pragma unroll
    for (int s = 0; s < 3; s++) { if (s < C) load(s, s); CP_COMMIT(); }

    const int l4 = lane >> 2, lm = lane & 3;
    const int a_off = (wr * 64 + l4) * ROWU2 + lm;
    const int g_off = 1536 + (wc * 16 + l4) * ROWU2 + lm;
    #pragma unroll 1
    for (int c = 0; c < C; c++) {
        CP_WAIT(2);
        __syncthreads();
        const int nc = c + 3;
        if (nc < C) load(nc, nc & 3);
        CP_COMMIT();
        const uint2* S = (const uint2*)(smem + 512 + (c & 3) * G1_STAGE);
        #pragma unroll
        for (int ks = 0; ks < 2; ks++) {
            uint32_t a[4][4];
            #pragma unroll
            for (int mi = 0; mi < 4; mi++) {
                const uint2 p = S[a_off + mi * (16 * ROWU2) + ks * 4];
                const uint2 q = S[a_off + mi * (16 * ROWU2) + 8 * ROWU2 + ks * 4];
                a[mi][0] = p.x; a[mi][1] = q.x; a[mi][2] = p.y; a[mi][3] = q.y;
            }
            #pragma unroll
            for (int ni = 0; ni < 2; ni++) {
                const uint2 vg = S[g_off + ni * (8 * ROWU2) + ks * 4];
                const uint2 vu = S[g_off + 768 + ni * (8 * ROWU2) + ks * 4];
                uint32_t bg[2] = { vg.x, vg.y };
                uint32_t bu[2] = { vu.x, vu.y };
                #pragma unroll
                for (int mi = 0; mi < 4; mi++) {
                    mma16(cg[mi][ni], a[mi], bg);
                    mma16(cu[mi][ni], a[mi], bu);
                }
            }
        }
    }
    // epilogue: silu(g)*u -> fp16 pair-permuted
    #pragma unroll
    for (int mi = 0; mi < 4; mi++)
        #pragma unroll
        for (int h = 0; h < 2; h++) {
            const int r = m0 + wr * 64 + mi * 16 + l4 + h * 8;
            if (r >= M) continue;
            const float v0 = silu(cg[mi][0][2 * h + 0]) * cu[mi][0][2 * h + 0];
            const float v1 = silu(cg[mi][0][2 * h + 1]) * cu[mi][0][2 * h + 1];
            const float v2 = silu(cg[mi][1][2 * h + 0]) * cu[mi][1][2 * h + 0];
            const float v3 = silu(cg[mi][1][2 * h + 1]) * cu[mi][1][2 * h + 1];
            uint2 val = { h2u(__floats2half2_rn(v0, v1)), h2u(__floats2half2_rn(v2, v3)) };
            ((uint2*)(Ho + (size_t)r * ldH + n0 + wc * 16))[lm] = val;
        }
}

// ---------------- GEMM2 fp16 merged: routed z<16, shared z==16 -------------
// Tile 128M x 128N, Kc=32, 4-stage (unchanged R11). Atomic scatter for both.
#define G2_STAGE 24576
#define G2_SMEM  (1024 + 4 * G2_STAGE)
__global__ void __launch_bounds__(256, 2)
gemm2_h(const __half* __restrict__ Hr, const __half* __restrict__ Wd_r,
        const __half* __restrict__ Hs, const __half* __restrict__ Wd_s,
        float* __restrict__ Out) {
    const int e = blockIdx.z;
    const bool SH = (e == NE);
    int M, K;
    const __half *Hin, *Wd;
    if (SH) {
        M = NT; K = SID; Hin = Hs; Wd = Wd_s;
    } else {
        M = d_cnt[e]; K = ID;
        Hin = Hr + (size_t)e * NT * ID;
        Wd  = Wd_r + (size_t)e * HD * ID;
    }
    const int m0 = blockIdx.y * 128;
    if (m0 >= M) return;
    const int n0 = blockIdx.x * 128;

    extern __shared__ char smem[];
    int*   s_tok = (int*)smem;
    float* s_wt  = (float*)(smem + 512);
    const int tid = threadIdx.x, lane = tid & 31, wid = tid >> 5;
    const int wr = wid >> 2, wc = wid & 3;
    if (tid < 128) {
        const bool ok = m0 + tid < M;
        if (SH) { s_tok[tid] = ok ? m0 + tid : 0; s_wt[tid] = 1.f; }
        else {
            s_tok[tid] = ok ? d_tok[e * NT + m0 + tid] : 0;
            s_wt [tid] = ok ? d_wt [e * NT + m0 + tid] : 0.f;
        }
    }
    __syncthreads();

    const int rA = tid >> 1, sA = (tid & 1) * 2;
    const bool aok = (m0 + rA) < M;
    const char* Ap = (const char*)(Hin + (size_t)(aok ? m0 + rA : 0) * K);
    const char* Bp = (const char*)(Wd + (size_t)(n0 + rA) * K);
    const uint32_t sb = smem_u32(smem) + 1024;
    const uint32_t dA = sb + rA * ROWB + sA * 16;
    const uint32_t dB = sb + 12288 + rA * ROWB + sA * 16;
    const uint32_t szA = aok ? 16u : 0u;

    const int C = K >> 5;
    auto load = [&](int c, int buf) {
        const int off = c * 64;
        const uint32_t b = buf * G2_STAGE;
        CP_ASYNC(dA + b,      Ap + off + sA * 16,      szA);
        CP_ASYNC(dA + b + 16, Ap + off + sA * 16 + 16, szA);
        CP_ASYNC(dB + b,      Bp + off + sA * 16,      16);
        CP_ASYNC(dB + b + 16, Bp + off + sA * 16 + 16, 16);
    };

    float acc[4][4][4] = {};
    #pragma unroll
    for (int s = 0; s < 3; s++) { if (s < C) load(s, s); CP_COMMIT(); }

    const int l4 = lane >> 2, lm = lane & 3;
    const int a_off = (wr * 64 + l4) * ROWU2 + lm;
    const int b_off = 1536 + (wc * 32 + l4) * ROWU2 + lm;
    #pragma unroll 1
    for (int c = 0; c < C; c++) {
        CP_WAIT(2);
        __syncthreads();
        const int nc = c + 3;
        if (nc < C) load(nc, nc & 3);
        CP_COMMIT();
        const uint2* S = (const uint2*)(smem + 1024 + (c & 3) * G2_STAGE);
        #pragma unroll
        for (int ks = 0; ks < 2; ks++) {
            uint32_t a[4][4];
            #pragma unroll
            for (int mi = 0; mi < 4; mi++) {
                const uint2 p = S[a_off + mi * (16 * ROWU2) + ks * 4];
                const uint2 q = S[a_off + mi * (16 * ROWU2) + 8 * ROWU2 + ks * 4];
                a[mi][0] = p.x; a[mi][1] = q.x; a[mi][2] = p.y; a[mi][3] = q.y;
            }
            #pragma unroll
            for (int ni = 0; ni < 4; ni++) {
                const uint2 vb = S[b_off + ni * (8 * ROWU2) + ks * 4];
                uint32_t b[2] = { vb.x, vb.y };
                #pragma unroll
                for (int mi = 0; mi < 4; mi++)
                    mma16(acc[mi][ni], a[mi], b);
            }
        }
    }
    #pragma unroll
    for (int mi = 0; mi < 4; mi++) {
        const int rl0 = wr * 64 + mi * 16 + l4;
        #pragma unroll
        for (int ni = 0; ni < 4; ni++) {
            const int cc = n0 + wc * 32 + ni * 8 + 2 * lm;
            #pragma unroll
            for (int h = 0; h < 2; h++) {
                const int rl = rl0 + h * 8;
                if (m0 + rl >= M) continue;
                const float w = s_wt[rl];
                float* o = Out + (size_t)s_tok[rl] * HD + cc;
                atomicAdd(o + 0, w * acc[mi][ni][2 * h + 0]);
                atomicAdd(o + 1, w * acc[mi][ni][2 * h + 1]);
            }
        }
    }
}

// ---------------- launch ----------------
extern "C" void kernel_launch(void* const* d_in, const int* in_sizes, int n_in,
                              void* d_out, int out_size) {
    const float* x       = (const float*)d_in[0];
    const float* gate_w  = (const float*)d_in[1];
    const float* gate_b  = (const float*)d_in[2];
    const float* w_gate  = (const float*)d_in[3];
    const float* w_up    = (const float*)d_in[4];
    const float* w_down  = (const float*)d_in[5];
    const float* sw_gate = (const float*)d_in[6];
    const float* sw_up   = (const float*)d_in[7];
    const float* sw_down = (const float*)d_in[8];
    float* out = (float*)d_out;

    __half *wg16, *wu16, *wd16, *sg16, *su16, *sd16, *xh, *hr, *hs;
    cudaGetSymbolAddress((void**)&wg16, w_g16);
    cudaGetSymbolAddress((void**)&wu16, w_u16);
    cudaGetSymbolAddress((void**)&wd16, w_d16);
    cudaGetSymbolAddress((void**)&sg16, sw_g16);
    cudaGetSymbolAddress((void**)&su16, sw_u16);
    cudaGetSymbolAddress((void**)&sd16, sw_d16);
    cudaGetSymbolAddress((void**)&xh,   x16);
    cudaGetSymbolAddress((void**)&hr,   h_r16);
    cudaGetSymbolAddress((void**)&hs,   h_s16);

    cudaFuncSetAttribute(gemm1_h, cudaFuncAttributeMaxDynamicSharedMemorySize, G1_SMEM);
    cudaFuncSetAttribute(gemm2_h, cudaFuncAttributeMaxDynamicSharedMemorySize, G2_SMEM);

    init_kernel<<<1, 32>>>();
    zero_out<<<(NT * HD) / 1024, 256>>>((float4*)out);
    conv_all<<<CONV_BLOCKS, 256>>>(
        (const float4*)w_gate, (const float4*)w_up, (const float4*)w_down,
        (const float4*)sw_gate, (const float4*)sw_up, (const float4*)sw_down,
        (const float4*)x,
        (uint4*)wg16, (uint4*)wu16, (uint4*)wd16,
        (uint4*)sg16, (uint4*)su16, (uint4*)sd16, (uint4*)xh);
    gate_kernel<<<NT, 512>>>(x, gate_w, gate_b);

    // merged gate/up + silu: z 0..15 routed (22 n-tiles used), z 16 shared (44)
    gemm1_h<<<dim3(SID / 64, NT / 128, NE + 1), 256, G1_SMEM>>>(
        xh, wg16, wu16, sg16, su16, hr, hs);
    // merged down: z 0..15 routed (K=ID), z 16 shared (K=SID); atomics into zeroed out
    gemm2_h<<<dim3(HD / 128, NT / 128, NE + 1), 256, G2_SMEM>>>(
        hr, wd16, hs, sd16, out);
}

// round 13
// speedup vs baseline: 1.3895x; 1.0160x over previous
#include <cuda_runtime.h>
#include <cuda_fp16.h>
#include <math.h>
#include <cstdint>

#define HD 2048
#define ID 1408
#define NE 16
#define TK 4
#define NT 1024
#define SID 2816
#define RSCALE 2.5f

// ---------------- scratch ----------------
__device__ int    d_cnt[NE];
__device__ int    d_tok[NE * NT];
__device__ float  d_wt [NE * NT];
// fp16 pair-permuted copies (K-groups of 16 stored as [p0,p4,p1,p5,p2,p6,p3,p7])
__device__ __half w_g16[NE * ID * HD];
__device__ __half w_u16[NE * ID * HD];
__device__ __half w_d16[NE * HD * ID];
__device__ __half sw_g16[SID * HD];
__device__ __half sw_u16[SID * HD];
__device__ __half sw_d16[HD * SID];
__device__ __half x16  [NT * HD];
__device__ __half h_r16[NE * NT * ID];
__device__ __half h_s16[NT * SID];

// ---------------- PTX helpers ----------------
__device__ __forceinline__ uint32_t smem_u32(const void* p) {
    uint32_t a;
    asm("{ .reg .u64 t; cvta.to.shared.u64 t, %1; cvt.u32.u64 %0, t; }"
        : "=r"(a) : "l"(p));
    return a;
}
#define CP_ASYNC(dst, src, sz) \
    asm volatile("cp.async.cg.shared.global [%0], [%1], 16, %2;" \
                 :: "r"(dst), "l"(src), "r"(sz) : "memory")
#define CP_COMMIT() asm volatile("cp.async.commit_group;" ::: "memory")
#define CP_WAIT(n)  asm volatile("cp.async.wait_group %0;" :: "n"(n) : "memory")

__device__ __forceinline__ void mma16(float* c, const uint32_t* a, const uint32_t* b) {
    asm volatile(
        "mma.sync.aligned.m16n8k16.row.col.f32.f16.f16.f32 "
        "{%0,%1,%2,%3}, {%4,%5,%6,%7}, {%8,%9}, {%0,%1,%2,%3};"
        : "+f"(c[0]), "+f"(c[1]), "+f"(c[2]), "+f"(c[3])
        : "r"(a[0]), "r"(a[1]), "r"(a[2]), "r"(a[3]), "r"(b[0]), "r"(b[1]));
}
__device__ __forceinline__ float silu(float g) { return g / (1.f + __expf(-g)); }
__device__ __forceinline__ uint32_t h2u(__half2 h) {
    uint32_t u; *(__half2*)&u = h; return u;
}

// smem rows: 64B data (32 fp16, permuted) + 32B pad = 96B (12 uint2)
#define ROWB 96
#define ROWU2 12

// ---------------- init ----------------
__global__ void init_kernel() {
    if (threadIdx.x < NE) d_cnt[threadIdx.x] = 0;
}

// ---------------- fused prologue: gate | zero_out | conversions -------------
// unit = 16 fp32 elements -> 16 fp16 pair-permuted
#define U_W ((size_t)NE * ID * HD / 16)
#define U_S ((size_t)SID * HD / 16)
#define U_X ((size_t)NT * HD / 16)
#define U_TOTAL (3 * U_W + 3 * U_S + U_X)
#define CONV_BLOCKS ((int)(U_TOTAL / 256))
#define ZERO_BLOCKS ((NT * HD) / 1024)          // 2048 blocks, 1 float4/thread
#define PRO_BLOCKS  (NT + ZERO_BLOCKS + CONV_BLOCKS)

__device__ __forceinline__ void conv_unit(const float4* __restrict__ s,
                                          uint4* __restrict__ d, size_t t) {
    float4 f0 = s[4 * t], f1 = s[4 * t + 1], f2 = s[4 * t + 2], f3 = s[4 * t + 3];
    const float f[16] = { f0.x, f0.y, f0.z, f0.w, f1.x, f1.y, f1.z, f1.w,
                          f2.x, f2.y, f2.z, f2.w, f3.x, f3.y, f3.z, f3.w };
    uint32_t h[8];
    #pragma unroll
    for (int q = 0; q < 8; q++) {
        const int j = (q & 1) ? ((q >> 1) + 4) : (q >> 1);
        h[q] = h2u(__floats2half2_rn(f[2 * j], f[2 * j + 1]));
    }
    d[2 * t]     = make_uint4(h[0], h[1], h[2], h[3]);
    d[2 * t + 1] = make_uint4(h[4], h[5], h[6], h[7]);
}

__device__ void gate_block(int t, const float* __restrict__ x,
                           const float* __restrict__ gw,
                           const float* __restrict__ gb) {
    __shared__ float s_sc[NE];
    const int wid = threadIdx.x >> 5, lane = threadIdx.x & 31;
    const float4* xr = (const float4*)(x + (size_t)t * HD);
    // 8 warps, each computes experts wid and wid+8
    #pragma unroll
    for (int eo = 0; eo < 2; eo++) {
        const int e = wid + eo * 8;
        const float4* wr = (const float4*)(gw + (size_t)e * HD);
        float acc = 0.f;
        #pragma unroll 4
        for (int k = lane; k < HD / 4; k += 32) {
            float4 a = xr[k], b = wr[k];
            acc += a.x * b.x + a.y * b.y + a.z * b.z + a.w * b.w;
        }
        #pragma unroll
        for (int o = 16; o; o >>= 1) acc += __shfl_xor_sync(0xffffffffu, acc, o);
        if (lane == 0) s_sc[e] = 1.f / (1.f + expf(-acc)) + gb[e];
    }
    __syncthreads();
    if (threadIdx.x != 0) return;

    float sc[NE];
    #pragma unroll
    for (int e = 0; e < NE; e++) sc[e] = s_sc[e];
    float gs[4];
    #pragma unroll
    for (int g = 0; g < 4; g++) {
        float m = sc[g * 4];
        #pragma unroll
        for (int j = 1; j < 4; j++) m = fmaxf(m, sc[g * 4 + j]);
        gs[g] = m;
    }
    int g0 = 0;
    for (int g = 1; g < 4; g++) if (gs[g] > gs[g0]) g0 = g;
    int g1 = -1;
    for (int g = 0; g < 4; g++) {
        if (g == g0) continue;
        if (g1 < 0 || gs[g] > gs[g1]) g1 = g;
    }
    float masked[NE];
    #pragma unroll
    for (int e = 0; e < NE; e++) {
        int g = e >> 2;
        masked[e] = (g == g0 || g == g1) ? sc[e] : 0.f;
    }
    int idx[TK]; float w[TK]; bool used[NE];
    #pragma unroll
    for (int e = 0; e < NE; e++) used[e] = false;
    float wsum = 0.f;
    for (int k = 0; k < TK; k++) {
        int best = -1;
        for (int e = 0; e < NE; e++) {
            if (used[e]) continue;
            if (best < 0 || masked[e] > masked[best]) best = e;
        }
        used[best] = true;
        idx[k] = best; w[k] = masked[best]; wsum += masked[best];
    }
    const float inv = 1.f / (wsum + 1e-6f);
    for (int k = 0; k < TK; k++) {
        int e = idx[k];
        int pos = atomicAdd(&d_cnt[e], 1);
        d_tok[e * NT + pos] = t;
        d_wt [e * NT + pos] = w[k] * inv * RSCALE;
    }
}

__global__ void prologue(const float* x, const float* gate_w, const float* gate_b,
                         float4* out,
                         const float4* wg, const float4* wu, const float4* wd,
                         const float4* sg, const float4* su, const float4* sd,
                         uint4* owg, uint4* owu, uint4* owd,
                         uint4* osg, uint4* osu, uint4* osd, uint4* oxx) {
    const int b = blockIdx.x;
    if (b < NT) { gate_block(b, x, gate_w, gate_b); return; }
    if (b < NT + ZERO_BLOCKS) {
        out[(size_t)(b - NT) * 256 + threadIdx.x] = make_float4(0.f, 0.f, 0.f, 0.f);
        return;
    }
    size_t u = (size_t)(b - NT - ZERO_BLOCKS) * 256 + threadIdx.x;
    if (u < U_W) { conv_unit(wg, owg, u); return; }
    u -= U_W;
    if (u < U_W) { conv_unit(wu, owu, u); return; }
    u -= U_W;
    if (u < U_W) { conv_unit(wd, owd, u); return; }
    u -= U_W;
    if (u < U_S) { conv_unit(sg, osg, u); return; }
    u -= U_S;
    if (u < U_S) { conv_unit(su, osu, u); return; }
    u -= U_S;
    if (u < U_S) { conv_unit(sd, osd, u); return; }
    u -= U_S;
    conv_unit((const float4*)x, oxx, u);
}

// ---------------- GEMM1 fp16: routed z<16, shared z=16/17 halves -----------
// Tile 128M x 64N dual, Kc=32, 4-stage cp.async (R12 mainloop, unchanged).
#define G1_STAGE 24576
#define G1_SMEM  (512 + 4 * G1_STAGE)
__global__ void __launch_bounds__(256, 2)
gemm1_h(const __half* __restrict__ X,
        const __half* __restrict__ Wg_r, const __half* __restrict__ Wu_r,
        const __half* __restrict__ Wg_s, const __half* __restrict__ Wu_s,
        __half* __restrict__ Hr, __half* __restrict__ Hs) {
    const int e = blockIdx.z;
    const bool SH = (e >= NE);
    int M, ldH, n0;
    const __half *Wg, *Wu; __half* Ho;
    if (SH) {
        M = NT; ldH = SID;
        Wg = Wg_s; Wu = Wu_s; Ho = Hs;
        n0 = ((int)blockIdx.x + (e == NE + 1 ? 22 : 0)) * 64;
    } else {
        M = d_cnt[e]; ldH = ID;
        Wg = Wg_r + (size_t)e * ID * HD;
        Wu = Wu_r + (size_t)e * ID * HD;
        Ho = Hr + (size_t)e * NT * ID;
        n0 = (int)blockIdx.x * 64;
    }
    const int m0 = blockIdx.y * 128;
    if (m0 >= M) return;
    const int K = HD;

    extern __shared__ char smem[];
    int* s_tok = (int*)smem;
    const int tid = threadIdx.x, lane = tid & 31, wid = tid >> 5;
    const int wr = wid >> 2, wc = wid & 3;
    if (!SH && tid < 128) s_tok[tid] = (m0 + tid < M) ? d_tok[e * NT + m0 + tid] : 0;
    __syncthreads();

    const int rA = tid >> 1, sA = (tid & 1) * 2;
    const int rW = tid >> 2, sW = tid & 3;
    const bool aok = (m0 + rA) < M;
    const int ar = SH ? (aok ? m0 + rA : 0) : (aok ? s_tok[rA] : 0);
    const char* Ap = (const char*)(X + (size_t)ar * K);
    const char* Gp = (const char*)(Wg + (size_t)(n0 + rW) * K);
    const char* Up = (const char*)(Wu + (size_t)(n0 + rW) * K);
    const uint32_t sb = smem_u32(smem) + 512;
    const uint32_t dA = sb + rA * ROWB + sA * 16;
    const uint32_t dG = sb + 12288 + rW * ROWB + sW * 16;
    const uint32_t dU = sb + 18432 + rW * ROWB + sW * 16;
    const uint32_t szA = aok ? 16u : 0u;

    const int C = K >> 5;
    auto load = [&](int c, int buf) {
        const int off = c * 64;
        const uint32_t b = buf * G1_STAGE;
        CP_ASYNC(dA + b,      Ap + off + sA * 16,      szA);
        CP_ASYNC(dA + b + 16, Ap + off + sA * 16 + 16, szA);
        CP_ASYNC(dG + b,      Gp + off + sW * 16, 16);
        CP_ASYNC(dU + b,      Up + off + sW * 16, 16);
    };

    float cg[4][2][4] = {}, cu[4][2][4] = {};
    #pragma unroll
    for (int s = 0; s < 3; s++) { if (s < C) load(s, s); CP_COMMIT(); }

    const int l4 = lane >> 2, lm = lane & 3;
    const int a_off = (wr * 64 + l4) * ROWU2 + lm;
    const int g_off = 1536 + (wc * 16 + l4) * ROWU2 + lm;
    #pragma unroll 1
    for (int c = 0; c < C; c++) {
        CP_WAIT(2);
        __syncthreads();
        const int nc = c + 3;
        if (nc < C) load(nc, nc & 3);
        CP_COMMIT();
        const uint2* S = (const uint2*)(smem + 512 + (c & 3) * G1_STAGE);
        #pragma unroll
        for (int ks = 0; ks < 2; ks++) {
            uint32_t a[4][4];
            #pragma unroll
            for (int mi = 0; mi < 4; mi++) {
                const uint2 p = S[a_off + mi * (16 * ROWU2) + ks * 4];
                const uint2 q = S[a_off + mi * (16 * ROWU2) + 8 * ROWU2 + ks * 4];
                a[mi][0] = p.x; a[mi][1] = q.x; a[mi][2] = p.y; a[mi][3] = q.y;
            }
            #pragma unroll
            for (int ni = 0; ni < 2; ni++) {
                const uint2 vg = S[g_off + ni * (8 * ROWU2) + ks * 4];
                const uint2 vu = S[g_off + 768 + ni * (8 * ROWU2) + ks * 4];
                uint32_t bg[2] = { vg.x, vg.y };
                uint32_t bu[2] = { vu.x, vu.y };
                #pragma unroll
                for (int mi = 0; mi < 4; mi++) {
                    mma16(cg[mi][ni], a[mi], bg);
                    mma16(cu[mi][ni], a[mi], bu);
                }
            }
        }
    }
    #pragma unroll
    for (int mi = 0; mi < 4; mi++)
        #pragma unroll
        for (int h = 0; h < 2; h++) {
            const int r = m0 + wr * 64 + mi * 16 + l4 + h * 8;
            if (r >= M) continue;
            const float v0 = silu(cg[mi][0][2 * h + 0]) * cu[mi][0][2 * h + 0];
            const float v1 = silu(cg[mi][0][2 * h + 1]) * cu[mi][0][2 * h + 1];
            const float v2 = silu(cg[mi][1][2 * h + 0]) * cu[mi][1][2 * h + 0];
            const float v3 = silu(cg[mi][1][2 * h + 1]) * cu[mi][1][2 * h + 1];
            uint2 val = { h2u(__floats2half2_rn(v0, v1)), h2u(__floats2half2_rn(v2, v3)) };
            ((uint2*)(Ho + (size_t)r * ldH + n0 + wc * 16))[lm] = val;
        }
}

// ---------------- GEMM2 fp16: routed z<16, shared z==16 (R12, unchanged) ---
#define G2_STAGE 24576
#define G2_SMEM  (1024 + 4 * G2_STAGE)
__global__ void __launch_bounds__(256, 2)
gemm2_h(const __half* __restrict__ Hr, const __half* __restrict__ Wd_r,
        const __half* __restrict__ Hs, const __half* __restrict__ Wd_s,
        float* __restrict__ Out) {
    const int e = blockIdx.z;
    const bool SH = (e == NE);
    int M, K;
    const __half *Hin, *Wd;
    if (SH) {
        M = NT; K = SID; Hin = Hs; Wd = Wd_s;
    } else {
        M = d_cnt[e]; K = ID;
        Hin = Hr + (size_t)e * NT * ID;
        Wd  = Wd_r + (size_t)e * HD * ID;
    }
    const int m0 = blockIdx.y * 128;
    if (m0 >= M) return;
    const int n0 = blockIdx.x * 128;

    extern __shared__ char smem[];
    int*   s_tok = (int*)smem;
    float* s_wt  = (float*)(smem + 512);
    const int tid = threadIdx.x, lane = tid & 31, wid = tid >> 5;
    const int wr = wid >> 2, wc = wid & 3;
    if (tid < 128) {
        const bool ok = m0 + tid < M;
        if (SH) { s_tok[tid] = ok ? m0 + tid : 0; s_wt[tid] = 1.f; }
        else {
            s_tok[tid] = ok ? d_tok[e * NT + m0 + tid] : 0;
            s_wt [tid] = ok ? d_wt [e * NT + m0 + tid] : 0.f;
        }
    }
    __syncthreads();

    const int rA = tid >> 1, sA = (tid & 1) * 2;
    const bool aok = (m0 + rA) < M;
    const char* Ap = (const char*)(Hin + (size_t)(aok ? m0 + rA : 0) * K);
    const char* Bp = (const char*)(Wd + (size_t)(n0 + rA) * K);
    const uint32_t sb = smem_u32(smem) + 1024;
    const uint32_t dA = sb + rA * ROWB + sA * 16;
    const uint32_t dB = sb + 12288 + rA * ROWB + sA * 16;
    const uint32_t szA = aok ? 16u : 0u;

    const int C = K >> 5;
    auto load = [&](int c, int buf) {
        const int off = c * 64;
        const uint32_t b = buf * G2_STAGE;
        CP_ASYNC(dA + b,      Ap + off + sA * 16,      szA);
        CP_ASYNC(dA + b + 16, Ap + off + sA * 16 + 16, szA);
        CP_ASYNC(dB + b,      Bp + off + sA * 16,      16);
        CP_ASYNC(dB + b + 16, Bp + off + sA * 16 + 16, 16);
    };

    float acc[4][4][4] = {};
    #pragma unroll
    for (int s = 0; s < 3; s++) { if (s < C) load(s, s); CP_COMMIT(); }

    const int l4 = lane >> 2, lm = lane & 3;
    const int a_off = (wr * 64 + l4) * ROWU2 + lm;
    const int b_off = 1536 + (wc * 32 + l4) * ROWU2 + lm;
    #pragma unroll 1
    for (int c = 0; c < C; c++) {
        CP_WAIT(2);
        __syncthreads();
        const int nc = c + 3;
        if (nc < C) load(nc, nc & 3);
        CP_COMMIT();
        const uint2* S = (const uint2*)(smem + 1024 + (c & 3) * G2_STAGE);
        #pragma unroll
        for (int ks = 0; ks < 2; ks++) {
            uint32_t a[4][4];
            #pragma unroll
            for (int mi = 0; mi < 4; mi++) {
                const uint2 p = S[a_off + mi * (16 * ROWU2) + ks * 4];
                const uint2 q = S[a_off + mi * (16 * ROWU2) + 8 * ROWU2 + ks * 4];
                a[mi][0] = p.x; a[mi][1] = q.x; a[mi][2] = p.y; a[mi][3] = q.y;
            }
            #pragma unroll
            for (int ni = 0; ni < 4; ni++) {
                const uint2 vb = S[b_off + ni * (8 * ROWU2) + ks * 4];
                uint32_t b[2] = { vb.x, vb.y };
                #pragma unroll
                for (int mi = 0; mi < 4; mi++)
                    mma16(acc[mi][ni], a[mi], b);
            }
        }
    }
    #pragma unroll
    for (int mi = 0; mi < 4; mi++) {
        const int rl0 = wr * 64 + mi * 16 + l4;
        #pragma unroll
        for (int ni = 0; ni < 4; ni++) {
            const int cc = n0 + wc * 32 + ni * 8 + 2 * lm;
            #pragma unroll
            for (int h = 0; h < 2; h++) {
                const int rl = rl0 + h * 8;
                if (m0 + rl >= M) continue;
                const float w = s_wt[rl];
                float* o = Out + (size_t)s_tok[rl] * HD + cc;
                atomicAdd(o + 0, w * acc[mi][ni][2 * h + 0]);
                atomicAdd(o + 1, w * acc[mi][ni][2 * h + 1]);
            }
        }
    }
}

// ---------------- launch ----------------
extern "C" void kernel_launch(void* const* d_in, const int* in_sizes, int n_in,
                              void* d_out, int out_size) {
    const float* x       = (const float*)d_in[0];
    const float* gate_w  = (const float*)d_in[1];
    const float* gate_b  = (const float*)d_in[2];
    const float* w_gate  = (const float*)d_in[3];
    const float* w_up    = (const float*)d_in[4];
    const float* w_down  = (const float*)d_in[5];
    const float* sw_gate = (const float*)d_in[6];
    const float* sw_up   = (const float*)d_in[7];
    const float* sw_down = (const float*)d_in[8];
    float* out = (float*)d_out;

    __half *wg16, *wu16, *wd16, *sg16, *su16, *sd16, *xh, *hr, *hs;
    cudaGetSymbolAddress((void**)&wg16, w_g16);
    cudaGetSymbolAddress((void**)&wu16, w_u16);
    cudaGetSymbolAddress((void**)&wd16, w_d16);
    cudaGetSymbolAddress((void**)&sg16, sw_g16);
    cudaGetSymbolAddress((void**)&su16, sw_u16);
    cudaGetSymbolAddress((void**)&sd16, sw_d16);
    cudaGetSymbolAddress((void**)&xh,   x16);
    cudaGetSymbolAddress((void**)&hr,   h_r16);
    cudaGetSymbolAddress((void**)&hs,   h_s16);

    cudaFuncSetAttribute(gemm1_h, cudaFuncAttributeMaxDynamicSharedMemorySize, G1_SMEM);
    cudaFuncSetAttribute(gemm2_h, cudaFuncAttributeMaxDynamicSharedMemorySize, G2_SMEM);

    init_kernel<<<1, 32>>>();
    // fused: gate (blocks 0..1023) | zero out | conversions
    prologue<<<PRO_BLOCKS, 256>>>(
        x, gate_w, gate_b, (float4*)out,
        (const float4*)w_gate, (const float4*)w_up, (const float4*)w_down,
        (const float4*)sw_gate, (const float4*)sw_up, (const float4*)sw_down,
        (uint4*)wg16, (uint4*)wu16, (uint4*)wd16,
        (uint4*)sg16, (uint4*)su16, (uint4*)sd16, (uint4*)xh);

    // gate/up + silu: z 0..15 routed, z 16/17 shared halves (22 n-tiles each)
    gemm1_h<<<dim3(22, NT / 128, NE + 2), 256, G1_SMEM>>>(
        xh, wg16, wu16, sg16, su16, hr, hs);
    // down: z 0..15 routed (K=ID), z 16 shared (K=SID); atomics into zeroed out
    gemm2_h<<<dim3(HD / 128, NT / 128, NE + 1), 256, G2_SMEM>>>(
        hr, wd16, hs, sd16, out);
}

// round 14
// speedup vs baseline: 1.4358x; 1.0334x over previous
#include <cuda_runtime.h>
#include <cuda_fp16.h>
#include <math.h>
#include <cstdint>

#define HD 2048
#define ID 1408
#define NE 16
#define TK 4
#define NT 1024
#define SID 2816
#define RSCALE 2.5f

// ---------------- scratch ----------------
__device__ int    d_cnt[NE];
__device__ int    d_tok[NE * NT];
__device__ float  d_wt [NE * NT];
// fp16 pair-permuted copies (K-groups of 16 stored as [p0,p4,p1,p5,p2,p6,p3,p7])
__device__ __half w_g16[NE * ID * HD];
__device__ __half w_u16[NE * ID * HD];
__device__ __half w_d16[NE * HD * ID];
__device__ __half sw_g16[SID * HD];
__device__ __half sw_u16[SID * HD];
__device__ __half sw_d16[HD * SID];
__device__ __half x16  [NT * HD];
__device__ __half h_r16[NE * NT * ID];
__device__ __half h_s16[NT * SID];

// ---------------- PTX helpers ----------------
__device__ __forceinline__ uint32_t smem_u32(const void* p) {
    uint32_t a;
    asm("{ .reg .u64 t; cvta.to.shared.u64 t, %1; cvt.u32.u64 %0, t; }"
        : "=r"(a) : "l"(p));
    return a;
}
#define CP_ASYNC(dst, src, sz) \
    asm volatile("cp.async.cg.shared.global [%0], [%1], 16, %2;" \
                 :: "r"(dst), "l"(src), "r"(sz) : "memory")
#define CP_COMMIT() asm volatile("cp.async.commit_group;" ::: "memory")
#define CP_WAIT(n)  asm volatile("cp.async.wait_group %0;" :: "n"(n) : "memory")

__device__ __forceinline__ void mma16(float* c, const uint32_t* a, const uint32_t* b) {
    asm volatile(
        "mma.sync.aligned.m16n8k16.row.col.f32.f16.f16.f32 "
        "{%0,%1,%2,%3}, {%4,%5,%6,%7}, {%8,%9}, {%0,%1,%2,%3};"
        : "+f"(c[0]), "+f"(c[1]), "+f"(c[2]), "+f"(c[3])
        : "r"(a[0]), "r"(a[1]), "r"(a[2]), "r"(a[3]), "r"(b[0]), "r"(b[1]));
}
__device__ __forceinline__ void red_add2(float* o, float v0, float v1) {
    asm volatile("red.global.add.v2.f32 [%0], {%1, %2};"
                 :: "l"(o), "f"(v0), "f"(v1) : "memory");
}
__device__ __forceinline__ float silu(float g) { return g / (1.f + __expf(-g)); }
__device__ __forceinline__ uint32_t h2u(__half2 h) {
    uint32_t u; *(__half2*)&u = h; return u;
}

// smem rows: 64B data (32 fp16, permuted) + 32B pad = 96B (12 uint2)
#define ROWB 96
#define ROWU2 12

// ---------------- init ----------------
__global__ void init_kernel() {
    if (threadIdx.x < NE) d_cnt[threadIdx.x] = 0;
}

// ---------------- conversion unit -------------------------------------------
// unit = 16 fp32 elements -> 16 fp16 pair-permuted
#define U_W ((size_t)NE * ID * HD / 16)
#define U_S ((size_t)SID * HD / 16)
#define U_X ((size_t)NT * HD / 16)
#define U_PRO (2 * U_W + 3 * U_S + U_X)          // wd handled inside gemm1
#define CONV_BLOCKS ((int)(U_PRO / 256))
#define ZERO_BLOCKS ((NT * HD) / 1024)
#define PRO_BLOCKS  (NT + ZERO_BLOCKS + CONV_BLOCKS)
#define WD_ZSLICES  ((int)(U_W / 256 / 176))     // 64 z-slices of 22x8 CTAs

__device__ __forceinline__ void conv_unit(const float4* __restrict__ s,
                                          uint4* __restrict__ d, size_t t) {
    float4 f0 = s[4 * t], f1 = s[4 * t + 1], f2 = s[4 * t + 2], f3 = s[4 * t + 3];
    const float f[16] = { f0.x, f0.y, f0.z, f0.w, f1.x, f1.y, f1.z, f1.w,
                          f2.x, f2.y, f2.z, f2.w, f3.x, f3.y, f3.z, f3.w };
    uint32_t h[8];
    #pragma unroll
    for (int q = 0; q < 8; q++) {
        const int j = (q & 1) ? ((q >> 1) + 4) : (q >> 1);
        h[q] = h2u(__floats2half2_rn(f[2 * j], f[2 * j + 1]));
    }
    d[2 * t]     = make_uint4(h[0], h[1], h[2], h[3]);
    d[2 * t + 1] = make_uint4(h[4], h[5], h[6], h[7]);
}

// ---------------- fused prologue: gate | zero_out | conv(wg,wu,sg,su,sd,x) --
__device__ void gate_block(int t, const float* __restrict__ x,
                           const float* __restrict__ gw,
                           const float* __restrict__ gb) {
    __shared__ float s_sc[NE];
    const int wid = threadIdx.x >> 5, lane = threadIdx.x & 31;
    const float4* xr = (const float4*)(x + (size_t)t * HD);
    #pragma unroll
    for (int eo = 0; eo < 2; eo++) {
        const int e = wid + eo * 8;
        const float4* wr = (const float4*)(gw + (size_t)e * HD);
        float acc = 0.f;
        #pragma unroll 4
        for (int k = lane; k < HD / 4; k += 32) {
            float4 a = xr[k], b = wr[k];
            acc += a.x * b.x + a.y * b.y + a.z * b.z + a.w * b.w;
        }
        #pragma unroll
        for (int o = 16; o; o >>= 1) acc += __shfl_xor_sync(0xffffffffu, acc, o);
        if (lane == 0) s_sc[e] = 1.f / (1.f + expf(-acc)) + gb[e];
    }
    __syncthreads();
    if (threadIdx.x != 0) return;

    float sc[NE];
    #pragma unroll
    for (int e = 0; e < NE; e++) sc[e] = s_sc[e];
    float gs[4];
    #pragma unroll
    for (int g = 0; g < 4; g++) {
        float m = sc[g * 4];
        #pragma unroll
        for (int j = 1; j < 4; j++) m = fmaxf(m, sc[g * 4 + j]);
        gs[g] = m;
    }
    int g0 = 0;
    for (int g = 1; g < 4; g++) if (gs[g] > gs[g0]) g0 = g;
    int g1 = -1;
    for (int g = 0; g < 4; g++) {
        if (g == g0) continue;
        if (g1 < 0 || gs[g] > gs[g1]) g1 = g;
    }
    float masked[NE];
    #pragma unroll
    for (int e = 0; e < NE; e++) {
        int g = e >> 2;
        masked[e] = (g == g0 || g == g1) ? sc[e] : 0.f;
    }
    int idx[TK]; float w[TK]; bool used[NE];
    #pragma unroll
    for (int e = 0; e < NE; e++) used[e] = false;
    float wsum = 0.f;
    for (int k = 0; k < TK; k++) {
        int best = -1;
        for (int e = 0; e < NE; e++) {
            if (used[e]) continue;
            if (best < 0 || masked[e] > masked[best]) best = e;
        }
        used[best] = true;
        idx[k] = best; w[k] = masked[best]; wsum += masked[best];
    }
    const float inv = 1.f / (wsum + 1e-6f);
    for (int k = 0; k < TK; k++) {
        int e = idx[k];
        int pos = atomicAdd(&d_cnt[e], 1);
        d_tok[e * NT + pos] = t;
        d_wt [e * NT + pos] = w[k] * inv * RSCALE;
    }
}

__global__ void prologue(const float* x, const float* gate_w, const float* gate_b,
                         float4* out,
                         const float4* wg, const float4* wu,
                         const float4* sg, const float4* su, const float4* sd,
                         uint4* owg, uint4* owu,
                         uint4* osg, uint4* osu, uint4* osd, uint4* oxx) {
    const int b = blockIdx.x;
    if (b < NT) { gate_block(b, x, gate_w, gate_b); return; }
    if (b < NT + ZERO_BLOCKS) {
        out[(size_t)(b - NT) * 256 + threadIdx.x] = make_float4(0.f, 0.f, 0.f, 0.f);
        return;
    }
    size_t u = (size_t)(b - NT - ZERO_BLOCKS) * 256 + threadIdx.x;
    if (u < U_W) { conv_unit(wg, owg, u); return; }
    u -= U_W;
    if (u < U_W) { conv_unit(wu, owu, u); return; }
    u -= U_W;
    if (u < U_S) { conv_unit(sg, osg, u); return; }
    u -= U_S;
    if (u < U_S) { conv_unit(su, osu, u); return; }
    u -= U_S;
    if (u < U_S) { conv_unit(sd, osd, u); return; }
    u -= U_S;
    conv_unit((const float4*)x, oxx, u);
}

// ---------------- GEMM1 fp16: routed z<16, shared z=16/17, wd-conv z>=18 ---
// Tile 128M x 64N dual, Kc=32, 4-stage cp.async (mainloop unchanged).
#define G1_STAGE 24576
#define G1_SMEM  (512 + 4 * G1_STAGE)
__global__ void __launch_bounds__(256, 2)
gemm1_h(const __half* __restrict__ X,
        const __half* __restrict__ Wg_r, const __half* __restrict__ Wu_r,
        const __half* __restrict__ Wg_s, const __half* __restrict__ Wu_s,
        __half* __restrict__ Hr, __half* __restrict__ Hs,
        const float4* __restrict__ Wd32, uint4* __restrict__ oWd) {
    const int e = blockIdx.z;
    if (e >= NE + 2) {
        // w_down conversion, tail-filling gemm1's drain wave
        const size_t cid = ((size_t)(e - NE - 2) * 8 + blockIdx.y) * 22 + blockIdx.x;
        conv_unit(Wd32, oWd, cid * 256 + threadIdx.x);
        return;
    }
    const bool SH = (e >= NE);
    int M, ldH, n0;
    const __half *Wg, *Wu; __half* Ho;
    if (SH) {
        M = NT; ldH = SID;
        Wg = Wg_s; Wu = Wu_s; Ho = Hs;
        n0 = ((int)blockIdx.x + (e == NE + 1 ? 22 : 0)) * 64;
    } else {
        M = d_cnt[e]; ldH = ID;
        Wg = Wg_r + (size_t)e * ID * HD;
        Wu = Wu_r + (size_t)e * ID * HD;
        Ho = Hr + (size_t)e * NT * ID;
        n0 = (int)blockIdx.x * 64;
    }
    const int m0 = blockIdx.y * 128;
    if (m0 >= M) return;
    const int K = HD;

    extern __shared__ char smem[];
    int* s_tok = (int*)smem;
    const int tid = threadIdx.x, lane = tid & 31, wid = tid >> 5;
    const int wr = wid >> 2, wc = wid & 3;
    if (!SH && tid < 128) s_tok[tid] = (m0 + tid < M) ? d_tok[e * NT + m0 + tid] : 0;
    __syncthreads();

    const int rA = tid >> 1, sA = (tid & 1) * 2;
    const int rW = tid >> 2, sW = tid & 3;
    const bool aok = (m0 + rA) < M;
    const int ar = SH ? (aok ? m0 + rA : 0) : (aok ? s_tok[rA] : 0);
    const char* Ap = (const char*)(X + (size_t)ar * K);
    const char* Gp = (const char*)(Wg + (size_t)(n0 + rW) * K);
    const char* Up = (const char*)(Wu + (size_t)(n0 + rW) * K);
    const uint32_t sb = smem_u32(smem) + 512;
    const uint32_t dA = sb + rA * ROWB + sA * 16;
    const uint32_t dG = sb + 12288 + rW * ROWB + sW * 16;
    const uint32_t dU = sb + 18432 + rW * ROWB + sW * 16;
    const uint32_t szA = aok ? 16u : 0u;

    const int C = K >> 5;
    auto load = [&](int c, int buf) {
        const int off = c * 64;
        const uint32_t b = buf * G1_STAGE;
        CP_ASYNC(dA + b,      Ap + off + sA * 16,      szA);
        CP_ASYNC(dA + b + 16, Ap + off + sA * 16 + 16, szA);
        CP_ASYNC(dG + b,      Gp + off + sW * 16, 16);
        CP_ASYNC(dU + b,      Up + off + sW * 16, 16);
    };

    float cg[4][2][4] = {}, cu[4][2][4] = {};
    #pragma unroll
    for (int s = 0; s < 3; s++) { if (s < C) load(s, s); CP_COMMIT(); }

    const int l4 = lane >> 2, lm = lane & 3;
    const int a_off = (wr * 64 + l4) * ROWU2 + lm;
    const int g_off = 1536 + (wc * 16 + l4) * ROWU2 + lm;
    #pragma unroll 1
    for (int c = 0; c < C; c++) {
        CP_WAIT(2);
        __syncthreads();
        const int nc = c + 3;
        if (nc < C) load(nc, nc & 3);
        CP_COMMIT();
        const uint2* S = (const uint2*)(smem + 512 + (c & 3) * G1_STAGE);
        #pragma unroll
        for (int ks = 0; ks < 2; ks++) {
            uint32_t a[4][4];
            #pragma unroll
            for (int mi = 0; mi < 4; mi++) {
                const uint2 p = S[a_off + mi * (16 * ROWU2) + ks * 4];
                const uint2 q = S[a_off + mi * (16 * ROWU2) + 8 * ROWU2 + ks * 4];
                a[mi][0] = p.x; a[mi][1] = q.x; a[mi][2] = p.y; a[mi][3] = q.y;
            }
            #pragma unroll
            for (int ni = 0; ni < 2; ni++) {
                const uint2 vg = S[g_off + ni * (8 * ROWU2) + ks * 4];
                const uint2 vu = S[g_off + 768 + ni * (8 * ROWU2) + ks * 4];
                uint32_t bg[2] = { vg.x, vg.y };
                uint32_t bu[2] = { vu.x, vu.y };
                #pragma unroll
                for (int mi = 0; mi < 4; mi++) {
                    mma16(cg[mi][ni], a[mi], bg);
                    mma16(cu[mi][ni], a[mi], bu);
                }
            }
        }
    }
    #pragma unroll
    for (int mi = 0; mi < 4; mi++)
        #pragma unroll
        for (int h = 0; h < 2; h++) {
            const int r = m0 + wr * 64 + mi * 16 + l4 + h * 8;
            if (r >= M) continue;
            const float v0 = silu(cg[mi][0][2 * h + 0]) * cu[mi][0][2 * h + 0];
            const float v1 = silu(cg[mi][0][2 * h + 1]) * cu[mi][0][2 * h + 1];
            const float v2 = silu(cg[mi][1][2 * h + 0]) * cu[mi][1][2 * h + 0];
            const float v3 = silu(cg[mi][1][2 * h + 1]) * cu[mi][1][2 * h + 1];
            uint2 val = { h2u(__floats2half2_rn(v0, v1)), h2u(__floats2half2_rn(v2, v3)) };
            ((uint2*)(Ho + (size_t)r * ldH + n0 + wc * 16))[lm] = val;
        }
}

// ---------------- GEMM2 fp16: routed z<16, shared z==16; v2 reductions -----
#define G2_STAGE 24576
#define G2_SMEM  (1024 + 4 * G2_STAGE)
__global__ void __launch_bounds__(256, 2)
gemm2_h(const __half* __restrict__ Hr, const __half* __restrict__ Wd_r,
        const __half* __restrict__ Hs, const __half* __restrict__ Wd_s,
        float* __restrict__ Out) {
    const int e = blockIdx.z;
    const bool SH = (e == NE);
    int M, K;
    const __half *Hin, *Wd;
    if (SH) {
        M = NT; K = SID; Hin = Hs; Wd = Wd_s;
    } else {
        M = d_cnt[e]; K = ID;
        Hin = Hr + (size_t)e * NT * ID;
        Wd  = Wd_r + (size_t)e * HD * ID;
    }
    const int m0 = blockIdx.y * 128;
    if (m0 >= M) return;
    const int n0 = blockIdx.x * 128;

    extern __shared__ char smem[];
    int*   s_tok = (int*)smem;
    float* s_wt  = (float*)(smem + 512);
    const int tid = threadIdx.x, lane = tid & 31, wid = tid >> 5;
    const int wr = wid >> 2, wc = wid & 3;
    if (tid < 128) {
        const bool ok = m0 + tid < M;
        if (SH) { s_tok[tid] = ok ? m0 + tid : 0; s_wt[tid] = 1.f; }
        else {
            s_tok[tid] = ok ? d_tok[e * NT + m0 + tid] : 0;
            s_wt [tid] = ok ? d_wt [e * NT + m0 + tid] : 0.f;
        }
    }
    __syncthreads();

    const int rA = tid >> 1, sA = (tid & 1) * 2;
    const bool aok = (m0 + rA) < M;
    const char* Ap = (const char*)(Hin + (size_t)(aok ? m0 + rA : 0) * K);
    const char* Bp = (const char*)(Wd + (size_t)(n0 + rA) * K);
    const uint32_t sb = smem_u32(smem) + 1024;
    const uint32_t dA = sb + rA * ROWB + sA * 16;
    const uint32_t dB = sb + 12288 + rA * ROWB + sA * 16;
    const uint32_t szA = aok ? 16u : 0u;

    const int C = K >> 5;
    auto load = [&](int c, int buf) {
        const int off = c * 64;
        const uint32_t b = buf * G2_STAGE;
        CP_ASYNC(dA + b,      Ap + off + sA * 16,      szA);
        CP_ASYNC(dA + b + 16, Ap + off + sA * 16 + 16, szA);
        CP_ASYNC(dB + b,      Bp + off + sA * 16,      16);
        CP_ASYNC(dB + b + 16, Bp + off + sA * 16 + 16, 16);
    };

    float acc[4][4][4] = {};
    #pragma unroll
    for (int s = 0; s < 3; s++) { if (s < C) load(s, s); CP_COMMIT(); }

    const int l4 = lane >> 2, lm = lane & 3;
    const int a_off = (wr * 64 + l4) * ROWU2 + lm;
    const int b_off = 1536 + (wc * 32 + l4) * ROWU2 + lm;
    #pragma unroll 1
    for (int c = 0; c < C; c++) {
        CP_WAIT(2);
        __syncthreads();
        const int nc = c + 3;
        if (nc < C) load(nc, nc & 3);
        CP_COMMIT();
        const uint2* S = (const uint2*)(smem + 1024 + (c & 3) * G2_STAGE);
        #pragma unroll
        for (int ks = 0; ks < 2; ks++) {
            uint32_t a[4][4];
            #pragma unroll
            for (int mi = 0; mi < 4; mi++) {
                const uint2 p = S[a_off + mi * (16 * ROWU2) + ks * 4];
                const uint2 q = S[a_off + mi * (16 * ROWU2) + 8 * ROWU2 + ks * 4];
                a[mi][0] = p.x; a[mi][1] = q.x; a[mi][2] = p.y; a[mi][3] = q.y;
            }
            #pragma unroll
            for (int ni = 0; ni < 4; ni++) {
                const uint2 vb = S[b_off + ni * (8 * ROWU2) + ks * 4];
                uint32_t b[2] = { vb.x, vb.y };
                #pragma unroll
                for (int mi = 0; mi < 4; mi++)
                    mma16(acc[mi][ni], a[mi], b);
            }
        }
    }
    #pragma unroll
    for (int mi = 0; mi < 4; mi++) {
        const int rl0 = wr * 64 + mi * 16 + l4;
        #pragma unroll
        for (int ni = 0; ni < 4; ni++) {
            const int cc = n0 + wc * 32 + ni * 8 + 2 * lm;
            #pragma unroll
            for (int h = 0; h < 2; h++) {
                const int rl = rl0 + h * 8;
                if (m0 + rl >= M) continue;
                const float w = s_wt[rl];
                float* o = Out + (size_t)s_tok[rl] * HD + cc;
                red_add2(o, w * acc[mi][ni][2 * h + 0], w * acc[mi][ni][2 * h + 1]);
            }
        }
    }
}

// ---------------- launch ----------------
extern "C" void kernel_launch(void* const* d_in, const int* in_sizes, int n_in,
                              void* d_out, int out_size) {
    const float* x       = (const float*)d_in[0];
    const float* gate_w  = (const float*)d_in[1];
    const float* gate_b  = (const float*)d_in[2];
    const float* w_gate  = (const float*)d_in[3];
    const float* w_up    = (const float*)d_in[4];
    const float* w_down  = (const float*)d_in[5];
    const float* sw_gate = (const float*)d_in[6];
    const float* sw_up   = (const float*)d_in[7];
    const float* sw_down = (const float*)d_in[8];
    float* out = (float*)d_out;

    __half *wg16, *wu16, *wd16, *sg16, *su16, *sd16, *xh, *hr, *hs;
    cudaGetSymbolAddress((void**)&wg16, w_g16);
    cudaGetSymbolAddress((void**)&wu16, w_u16);
    cudaGetSymbolAddress((void**)&wd16, w_d16);
    cudaGetSymbolAddress((void**)&sg16, sw_g16);
    cudaGetSymbolAddress((void**)&su16, sw_u16);
    cudaGetSymbolAddress((void**)&sd16, sw_d16);
    cudaGetSymbolAddress((void**)&xh,   x16);
    cudaGetSymbolAddress((void**)&hr,   h_r16);
    cudaGetSymbolAddress((void**)&hs,   h_s16);

    cudaFuncSetAttribute(gemm1_h, cudaFuncAttributeMaxDynamicSharedMemorySize, G1_SMEM);
    cudaFuncSetAttribute(gemm2_h, cudaFuncAttributeMaxDynamicSharedMemorySize, G2_SMEM);

    init_kernel<<<1, 32>>>();
    // fused: gate | zero out | conversions (all except w_down)
    prologue<<<PRO_BLOCKS, 256>>>(
        x, gate_w, gate_b, (float4*)out,
        (const float4*)w_gate, (const float4*)w_up,
        (const float4*)sw_gate, (const float4*)sw_up, (const float4*)sw_down,
        (uint4*)wg16, (uint4*)wu16,
        (uint4*)sg16, (uint4*)su16, (uint4*)sd16, (uint4*)xh);

    // gate/up + silu: z 0..15 routed, z 16/17 shared halves, z 18.. wd-conv
    gemm1_h<<<dim3(22, NT / 128, NE + 2 + WD_ZSLICES), 256, G1_SMEM>>>(
        xh, wg16, wu16, sg16, su16, hr, hs,
        (const float4*)w_down, (uint4*)wd16);
    // down: z 0..15 routed (K=ID), z 16 shared (K=SID); v2 reductions into zeroed out
    gemm2_h<<<dim3(HD / 128, NT / 128, NE + 1), 256, G2_SMEM>>>(
        hr, wd16, hs, sd16, out);
}

// round 15
// speedup vs baseline: 1.4461x; 1.0072x over previous
#include <cuda_runtime.h>
#include <cuda_fp16.h>
#include <math.h>
#include <cstdint>

#define HD 2048
#define ID 1408
#define NE 16
#define TK 4
#define NT 1024
#define SID 2816
#define RSCALE 2.5f

// ---------------- scratch ----------------
__device__ int    d_cnt[NE];
__device__ int    d_tok[NE * NT];
__device__ float  d_wt [NE * NT];
// fp16 pair-permuted copies (K-groups of 16 stored as [p0,p4,p1,p5,p2,p6,p3,p7])
__device__ __half w_g16[NE * ID * HD];
__device__ __half w_u16[NE * ID * HD];
__device__ __half w_d16[NE * HD * ID];
__device__ __half sw_g16[SID * HD];
__device__ __half sw_u16[SID * HD];
__device__ __half sw_d16[HD * SID];
__device__ __half x16  [NT * HD];
__device__ __half h_r16[NE * NT * ID];
__device__ __half h_s16[NT * SID];

// ---------------- PTX helpers ----------------
__device__ __forceinline__ uint32_t smem_u32(const void* p) {
    uint32_t a;
    asm("{ .reg .u64 t; cvta.to.shared.u64 t, %1; cvt.u32.u64 %0, t; }"
        : "=r"(a) : "l"(p));
    return a;
}
#define CP_ASYNC(dst, src, sz) \
    asm volatile("cp.async.cg.shared.global [%0], [%1], 16, %2;" \
                 :: "r"(dst), "l"(src), "r"(sz) : "memory")
#define CP_COMMIT() asm volatile("cp.async.commit_group;" ::: "memory")
#define CP_WAIT(n)  asm volatile("cp.async.wait_group %0;" :: "n"(n) : "memory")

__device__ __forceinline__ void mma16(float* c, const uint32_t* a, const uint32_t* b) {
    asm volatile(
        "mma.sync.aligned.m16n8k16.row.col.f32.f16.f16.f32 "
        "{%0,%1,%2,%3}, {%4,%5,%6,%7}, {%8,%9}, {%0,%1,%2,%3};"
        : "+f"(c[0]), "+f"(c[1]), "+f"(c[2]), "+f"(c[3])
        : "r"(a[0]), "r"(a[1]), "r"(a[2]), "r"(a[3]), "r"(b[0]), "r"(b[1]));
}
__device__ __forceinline__ void red_add2(float* o, float v0, float v1) {
    asm volatile("red.global.add.v2.f32 [%0], {%1, %2};"
                 :: "l"(o), "f"(v0), "f"(v1) : "memory");
}
__device__ __forceinline__ float silu(float g) { return g / (1.f + __expf(-g)); }
__device__ __forceinline__ uint32_t h2u(__half2 h) {
    uint32_t u; *(__half2*)&u = h; return u;
}

// smem rows: 64B data (32 fp16, permuted) + 32B pad = 96B (12 uint2)
#define ROWB 96
#define ROWU2 12

// ---------------- init ----------------
__global__ void init_kernel() {
    if (threadIdx.x < NE) d_cnt[threadIdx.x] = 0;
}

// ---------------- conversion unit -------------------------------------------
#define U_W ((size_t)NE * ID * HD / 16)
#define U_S ((size_t)SID * HD / 16)
#define U_X ((size_t)NT * HD / 16)
#define U_PRO (2 * U_W + 3 * U_S + U_X)
#define CONV_BLOCKS ((int)(U_PRO / 256))
#define ZERO_BLOCKS ((NT * HD) / 1024)
#define PRO_BLOCKS  (NT + ZERO_BLOCKS + CONV_BLOCKS)
#define WD_ZSLICES  ((int)(U_W / 256 / 176))

__device__ __forceinline__ void conv_unit(const float4* __restrict__ s,
                                          uint4* __restrict__ d, size_t t) {
    float4 f0 = s[4 * t], f1 = s[4 * t + 1], f2 = s[4 * t + 2], f3 = s[4 * t + 3];
    const float f[16] = { f0.x, f0.y, f0.z, f0.w, f1.x, f1.y, f1.z, f1.w,
                          f2.x, f2.y, f2.z, f2.w, f3.x, f3.y, f3.z, f3.w };
    uint32_t h[8];
    #pragma unroll
    for (int q = 0; q < 8; q++) {
        const int j = (q & 1) ? ((q >> 1) + 4) : (q >> 1);
        h[q] = h2u(__floats2half2_rn(f[2 * j], f[2 * j + 1]));
    }
    d[2 * t]     = make_uint4(h[0], h[1], h[2], h[3]);
    d[2 * t + 1] = make_uint4(h[4], h[5], h[6], h[7]);
}

// ---------------- fused prologue: gate | zero_out | conv(wg,wu,sg,su,sd,x) --
__device__ void gate_block(int t, const float* __restrict__ x,
                           const float* __restrict__ gw,
                           const float* __restrict__ gb) {
    __shared__ float s_sc[NE];
    const int wid = threadIdx.x >> 5, lane = threadIdx.x & 31;
    const float4* xr = (const float4*)(x + (size_t)t * HD);
    #pragma unroll
    for (int eo = 0; eo < 2; eo++) {
        const int e = wid + eo * 8;
        const float4* wr = (const float4*)(gw + (size_t)e * HD);
        float acc = 0.f;
        #pragma unroll 4
        for (int k = lane; k < HD / 4; k += 32) {
            float4 a = xr[k], b = wr[k];
            acc += a.x * b.x + a.y * b.y + a.z * b.z + a.w * b.w;
        }
        #pragma unroll
        for (int o = 16; o; o >>= 1) acc += __shfl_xor_sync(0xffffffffu, acc, o);
        if (lane == 0) s_sc[e] = 1.f / (1.f + expf(-acc)) + gb[e];
    }
    __syncthreads();
    if (threadIdx.x != 0) return;

    float sc[NE];
    #pragma unroll
    for (int e = 0; e < NE; e++) sc[e] = s_sc[e];
    float gs[4];
    #pragma unroll
    for (int g = 0; g < 4; g++) {
        float m = sc[g * 4];
        #pragma unroll
        for (int j = 1; j < 4; j++) m = fmaxf(m, sc[g * 4 + j]);
        gs[g] = m;
    }
    int g0 = 0;
    for (int g = 1; g < 4; g++) if (gs[g] > gs[g0]) g0 = g;
    int g1 = -1;
    for (int g = 0; g < 4; g++) {
        if (g == g0) continue;
        if (g1 < 0 || gs[g] > gs[g1]) g1 = g;
    }
    float masked[NE];
    #pragma unroll
    for (int e = 0; e < NE; e++) {
        int g = e >> 2;
        masked[e] = (g == g0 || g == g1) ? sc[e] : 0.f;
    }
    int idx[TK]; float w[TK]; bool used[NE];
    #pragma unroll
    for (int e = 0; e < NE; e++) used[e] = false;
    float wsum = 0.f;
    for (int k = 0; k < TK; k++) {
        int best = -1;
        for (int e = 0; e < NE; e++) {
            if (used[e]) continue;
            if (best < 0 || masked[e] > masked[best]) best = e;
        }
        used[best] = true;
        idx[k] = best; w[k] = masked[best]; wsum += masked[best];
    }
    const float inv = 1.f / (wsum + 1e-6f);
    for (int k = 0; k < TK; k++) {
        int e = idx[k];
        int pos = atomicAdd(&d_cnt[e], 1);
        d_tok[e * NT + pos] = t;
        d_wt [e * NT + pos] = w[k] * inv * RSCALE;
    }
}

__global__ void prologue(const float* x, const float* gate_w, const float* gate_b,
                         float4* out,
                         const float4* wg, const float4* wu,
                         const float4* sg, const float4* su, const float4* sd,
                         uint4* owg, uint4* owu,
                         uint4* osg, uint4* osu, uint4* osd, uint4* oxx) {
    const int b = blockIdx.x;
    if (b < NT) { gate_block(b, x, gate_w, gate_b); return; }
    if (b < NT + ZERO_BLOCKS) {
        out[(size_t)(b - NT) * 256 + threadIdx.x] = make_float4(0.f, 0.f, 0.f, 0.f);
        return;
    }
    size_t u = (size_t)(b - NT - ZERO_BLOCKS) * 256 + threadIdx.x;
    if (u < U_W) { conv_unit(wg, owg, u); return; }
    u -= U_W;
    if (u < U_W) { conv_unit(wu, owu, u); return; }
    u -= U_W;
    if (u < U_S) { conv_unit(sg, osg, u); return; }
    u -= U_S;
    if (u < U_S) { conv_unit(su, osu, u); return; }
    u -= U_S;
    if (u < U_S) { conv_unit(sd, osd, u); return; }
    u -= U_S;
    conv_unit((const float4*)x, oxx, u);
}

// ---------------- GEMM1 fp16: routed z<16, shared z=16/17, wd-conv z>=18 ---
// Tile 128M x 64N dual, Kc=32, 4-stage cp.async (R14, unchanged).
#define G1_STAGE 24576
#define G1_SMEM  (512 + 4 * G1_STAGE)
__global__ void __launch_bounds__(256, 2)
gemm1_h(const __half* __restrict__ X,
        const __half* __restrict__ Wg_r, const __half* __restrict__ Wu_r,
        const __half* __restrict__ Wg_s, const __half* __restrict__ Wu_s,
        __half* __restrict__ Hr, __half* __restrict__ Hs,
        const float4* __restrict__ Wd32, uint4* __restrict__ oWd) {
    const int e = blockIdx.z;
    if (e >= NE + 2) {
        const size_t cid = ((size_t)(e - NE - 2) * 8 + blockIdx.y) * 22 + blockIdx.x;
        conv_unit(Wd32, oWd, cid * 256 + threadIdx.x);
        return;
    }
    const bool SH = (e >= NE);
    int M, ldH, n0;
    const __half *Wg, *Wu; __half* Ho;
    if (SH) {
        M = NT; ldH = SID;
        Wg = Wg_s; Wu = Wu_s; Ho = Hs;
        n0 = ((int)blockIdx.x + (e == NE + 1 ? 22 : 0)) * 64;
    } else {
        M = d_cnt[e]; ldH = ID;
        Wg = Wg_r + (size_t)e * ID * HD;
        Wu = Wu_r + (size_t)e * ID * HD;
        Ho = Hr + (size_t)e * NT * ID;
        n0 = (int)blockIdx.x * 64;
    }
    const int m0 = blockIdx.y * 128;
    if (m0 >= M) return;
    const int K = HD;

    extern __shared__ char smem[];
    int* s_tok = (int*)smem;
    const int tid = threadIdx.x, lane = tid & 31, wid = tid >> 5;
    const int wr = wid >> 2, wc = wid & 3;
    if (!SH && tid < 128) s_tok[tid] = (m0 + tid < M) ? d_tok[e * NT + m0 + tid] : 0;
    __syncthreads();

    const int rA = tid >> 1, sA = (tid & 1) * 2;
    const int rW = tid >> 2, sW = tid & 3;
    const bool aok = (m0 + rA) < M;
    const int ar = SH ? (aok ? m0 + rA : 0) : (aok ? s_tok[rA] : 0);
    const char* Ap = (const char*)(X + (size_t)ar * K);
    const char* Gp = (const char*)(Wg + (size_t)(n0 + rW) * K);
    const char* Up = (const char*)(Wu + (size_t)(n0 + rW) * K);
    const uint32_t sb = smem_u32(smem) + 512;
    const uint32_t dA = sb + rA * ROWB + sA * 16;
    const uint32_t dG = sb + 12288 + rW * ROWB + sW * 16;
    const uint32_t dU = sb + 18432 + rW * ROWB + sW * 16;
    const uint32_t szA = aok ? 16u : 0u;

    const int C = K >> 5;
    auto load = [&](int c, int buf) {
        const int off = c * 64;
        const uint32_t b = buf * G1_STAGE;
        CP_ASYNC(dA + b,      Ap + off + sA * 16,      szA);
        CP_ASYNC(dA + b + 16, Ap + off + sA * 16 + 16, szA);
        CP_ASYNC(dG + b,      Gp + off + sW * 16, 16);
        CP_ASYNC(dU + b,      Up + off + sW * 16, 16);
    };

    float cg[4][2][4] = {}, cu[4][2][4] = {};
    #pragma unroll
    for (int s = 0; s < 3; s++) { if (s < C) load(s, s); CP_COMMIT(); }

    const int l4 = lane >> 2, lm = lane & 3;
    const int a_off = (wr * 64 + l4) * ROWU2 + lm;
    const int g_off = 1536 + (wc * 16 + l4) * ROWU2 + lm;
    #pragma unroll 1
    for (int c = 0; c < C; c++) {
        CP_WAIT(2);
        __syncthreads();
        const int nc = c + 3;
        if (nc < C) load(nc, nc & 3);
        CP_COMMIT();
        const uint2* S = (const uint2*)(smem + 512 + (c & 3) * G1_STAGE);
        #pragma unroll
        for (int ks = 0; ks < 2; ks++) {
            uint32_t a[4][4];
            #pragma unroll
            for (int mi = 0; mi < 4; mi++) {
                const uint2 p = S[a_off + mi * (16 * ROWU2) + ks * 4];
                const uint2 q = S[a_off + mi * (16 * ROWU2) + 8 * ROWU2 + ks * 4];
                a[mi][0] = p.x; a[mi][1] = q.x; a[mi][2] = p.y; a[mi][3] = q.y;
            }
            #pragma unroll
            for (int ni = 0; ni < 2; ni++) {
                const uint2 vg = S[g_off + ni * (8 * ROWU2) + ks * 4];
                const uint2 vu = S[g_off + 768 + ni * (8 * ROWU2) + ks * 4];
                uint32_t bg[2] = { vg.x, vg.y };
                uint32_t bu[2] = { vu.x, vu.y };
                #pragma unroll
                for (int mi = 0; mi < 4; mi++) {
                    mma16(cg[mi][ni], a[mi], bg);
                    mma16(cu[mi][ni], a[mi], bu);
                }
            }
        }
    }
    #pragma unroll
    for (int mi = 0; mi < 4; mi++)
        #pragma unroll
        for (int h = 0; h < 2; h++) {
            const int r = m0 + wr * 64 + mi * 16 + l4 + h * 8;
            if (r >= M) continue;
            const float v0 = silu(cg[mi][0][2 * h + 0]) * cu[mi][0][2 * h + 0];
            const float v1 = silu(cg[mi][0][2 * h + 1]) * cu[mi][0][2 * h + 1];
            const float v2 = silu(cg[mi][1][2 * h + 0]) * cu[mi][1][2 * h + 0];
            const float v3 = silu(cg[mi][1][2 * h + 1]) * cu[mi][1][2 * h + 1];
            uint2 val = { h2u(__floats2half2_rn(v0, v1)), h2u(__floats2half2_rn(v2, v3)) };
            ((uint2*)(Ho + (size_t)r * ldH + n0 + wc * 16))[lm] = val;
        }
}

// ---------------- GEMM2 fp16: tile 128M x 64N, 3 CTAs/SM -------------------
// z=0 shared (K=SID, longest CTAs start in wave 1), z=1..16 routed e=z-1.
// Stage 18432B: A 128x96 @0 | B 64x96 @12288. 4 stages.
#define G2_STAGE 18432
#define G2_SMEM  (1024 + 4 * G2_STAGE)
__global__ void __launch_bounds__(256, 3)
gemm2_h(const __half* __restrict__ Hr, const __half* __restrict__ Wd_r,
        const __half* __restrict__ Hs, const __half* __restrict__ Wd_s,
        float* __restrict__ Out) {
    const int zz = blockIdx.z;
    const bool SH = (zz == 0);
    const int e = SH ? 0 : zz - 1;
    int M, K;
    const __half *Hin, *Wd;
    if (SH) {
        M = NT; K = SID; Hin = Hs; Wd = Wd_s;
    } else {
        M = d_cnt[e]; K = ID;
        Hin = Hr + (size_t)e * NT * ID;
        Wd  = Wd_r + (size_t)e * HD * ID;
    }
    const int m0 = blockIdx.y * 128;
    if (m0 >= M) return;
    const int n0 = blockIdx.x * 64;

    extern __shared__ char smem[];
    int*   s_tok = (int*)smem;
    float* s_wt  = (float*)(smem + 512);
    const int tid = threadIdx.x, lane = tid & 31, wid = tid >> 5;
    const int wr = wid >> 2, wc = wid & 3;
    if (tid < 128) {
        const bool ok = m0 + tid < M;
        if (SH) { s_tok[tid] = ok ? m0 + tid : 0; s_wt[tid] = 1.f; }
        else {
            s_tok[tid] = ok ? d_tok[e * NT + m0 + tid] : 0;
            s_wt [tid] = ok ? d_wt [e * NT + m0 + tid] : 0.f;
        }
    }
    __syncthreads();

    const int rA = tid >> 1, sA = (tid & 1) * 2;
    const int rB = tid >> 2, sB = tid & 3;
    const bool aok = (m0 + rA) < M;
    const char* Ap = (const char*)(Hin + (size_t)(aok ? m0 + rA : 0) * K);
    const char* Bp = (const char*)(Wd + (size_t)(n0 + rB) * K);
    const uint32_t sb = smem_u32(smem) + 1024;
    const uint32_t dA = sb + rA * ROWB + sA * 16;
    const uint32_t dB = sb + 12288 + rB * ROWB + sB * 16;
    const uint32_t szA = aok ? 16u : 0u;

    const int C = K >> 5;
    auto load = [&](int c, int buf) {
        const int off = c * 64;
        const uint32_t b = buf * G2_STAGE;
        CP_ASYNC(dA + b,      Ap + off + sA * 16,      szA);
        CP_ASYNC(dA + b + 16, Ap + off + sA * 16 + 16, szA);
        CP_ASYNC(dB + b,      Bp + off + sB * 16, 16);
    };

    float acc[4][2][4] = {};
    #pragma unroll
    for (int s = 0; s < 3; s++) { if (s < C) load(s, s); CP_COMMIT(); }

    const int l4 = lane >> 2, lm = lane & 3;
    const int a_off = (wr * 64 + l4) * ROWU2 + lm;
    const int b_off = 1536 + (wc * 16 + l4) * ROWU2 + lm;
    #pragma unroll 1
    for (int c = 0; c < C; c++) {
        CP_WAIT(2);
        __syncthreads();
        const int nc = c + 3;
        if (nc < C) load(nc, nc & 3);
        CP_COMMIT();
        const uint2* S = (const uint2*)(smem + 1024 + (c & 3) * G2_STAGE);
        #pragma unroll
        for (int ks = 0; ks < 2; ks++) {
            uint32_t a[4][4];
            #pragma unroll
            for (int mi = 0; mi < 4; mi++) {
                const uint2 p = S[a_off + mi * (16 * ROWU2) + ks * 4];
                const uint2 q = S[a_off + mi * (16 * ROWU2) + 8 * ROWU2 + ks * 4];
                a[mi][0] = p.x; a[mi][1] = q.x; a[mi][2] = p.y; a[mi][3] = q.y;
            }
            #pragma unroll
            for (int ni = 0; ni < 2; ni++) {
                const uint2 vb = S[b_off + ni * (8 * ROWU2) + ks * 4];
                uint32_t b[2] = { vb.x, vb.y };
                #pragma unroll
                for (int mi = 0; mi < 4; mi++)
                    mma16(acc[mi][ni], a[mi], b);
            }
        }
    }
    #pragma unroll
    for (int mi = 0; mi < 4; mi++) {
        const int rl0 = wr * 64 + mi * 16 + l4;
        #pragma unroll
        for (int ni = 0; ni < 2; ni++) {
            const int cc = n0 + wc * 16 + ni * 8 + 2 * lm;
            #pragma unroll
            for (int h = 0; h < 2; h++) {
                const int rl = rl0 + h * 8;
                if (m0 + rl >= M) continue;
                const float w = s_wt[rl];
                float* o = Out + (size_t)s_tok[rl] * HD + cc;
                red_add2(o, w * acc[mi][ni][2 * h + 0], w * acc[mi][ni][2 * h + 1]);
            }
        }
    }
}

// ---------------- launch ----------------
extern "C" void kernel_launch(void* const* d_in, const int* in_sizes, int n_in,
                              void* d_out, int out_size) {
    const float* x       = (const float*)d_in[0];
    const float* gate_w  = (const float*)d_in[1];
    const float* gate_b  = (const float*)d_in[2];
    const float* w_gate  = (const float*)d_in[3];
    const float* w_up    = (const float*)d_in[4];
    const float* w_down  = (const float*)d_in[5];
    const float* sw_gate = (const float*)d_in[6];
    const float* sw_up   = (const float*)d_in[7];
    const float* sw_down = (const float*)d_in[8];
    float* out = (float*)d_out;

    __half *wg16, *wu16, *wd16, *sg16, *su16, *sd16, *xh, *hr, *hs;
    cudaGetSymbolAddress((void**)&wg16, w_g16);
    cudaGetSymbolAddress((void**)&wu16, w_u16);
    cudaGetSymbolAddress((void**)&wd16, w_d16);
    cudaGetSymbolAddress((void**)&sg16, sw_g16);
    cudaGetSymbolAddress((void**)&su16, sw_u16);
    cudaGetSymbolAddress((void**)&sd16, sw_d16);
    cudaGetSymbolAddress((void**)&xh,   x16);
    cudaGetSymbolAddress((void**)&hr,   h_r16);
    cudaGetSymbolAddress((void**)&hs,   h_s16);

    cudaFuncSetAttribute(gemm1_h, cudaFuncAttributeMaxDynamicSharedMemorySize, G1_SMEM);
    cudaFuncSetAttribute(gemm2_h, cudaFuncAttributeMaxDynamicSharedMemorySize, G2_SMEM);

    init_kernel<<<1, 32>>>();
    prologue<<<PRO_BLOCKS, 256>>>(
        x, gate_w, gate_b, (float4*)out,
        (const float4*)w_gate, (const float4*)w_up,
        (const float4*)sw_gate, (const float4*)sw_up, (const float4*)sw_down,
        (uint4*)wg16, (uint4*)wu16,
        (uint4*)sg16, (uint4*)su16, (uint4*)sd16, (uint4*)xh);

    // gate/up + silu: z 0..15 routed, z 16/17 shared halves, z 18.. wd-conv
    gemm1_h<<<dim3(22, NT / 128, NE + 2 + WD_ZSLICES), 256, G1_SMEM>>>(
        xh, wg16, wu16, sg16, su16, hr, hs,
        (const float4*)w_down, (uint4*)wd16);
    // down: z=0 shared (K=SID), z=1..16 routed (K=ID); v2 reductions into zeroed out
    gemm2_h<<<dim3(HD / 64, NT / 128, NE + 1), 256, G2_SMEM>>>(
        hr, wd16, hs, sd16, out);
}